// round 1
// baseline (speedup 1.0000x reference)
#include <cuda_runtime.h>
#include <math_constants.h>

#define S_N   8192
#define SRC   768
#define DK    128
#define DV    64

typedef unsigned long long ull;

// ---------------- scratch (no allocations allowed) ----------------
__device__ float g_Q[S_N * DK];    // 4 MB
__device__ float g_K[S_N * DK];    // 4 MB
__device__ float g_vs[S_N];        // scalar V per key
__device__ float g_out[S_N];       // gate scalar per query
__device__ float g_wvo[SRC];       // w_output @ w_v
__device__ float g_x2sum;

// ---------------- f32x2 packed helpers (sm_103a) -------------------
__device__ __forceinline__ ull pk2(float x, float y) {
    ull r;
    asm("mov.b64 %0, {%1, %2};" : "=l"(r) : "f"(x), "f"(y));
    return r;
}
__device__ __forceinline__ void upk2(ull v, float& x, float& y) {
    asm("mov.b64 {%0, %1}, %2;" : "=f"(x), "=f"(y) : "l"(v));
}
__device__ __forceinline__ ull ffma2(ull a, ull b, ull c) {
    ull d;
    asm("fma.rn.f32x2 %0, %1, %2, %3;" : "=l"(d) : "l"(a), "l"(b), "l"(c));
    return d;
}

// ---------------- kernel 1: wvo = w_output @ w_v; zero flag --------
__global__ void prep_kernel(const float* __restrict__ w_v,
                            const float* __restrict__ w_out) {
    int c = threadIdx.x;
    if (c == 0) g_x2sum = 0.0f;
    if (c < SRC) {
        float acc = 0.0f;
        #pragma unroll
        for (int j = 0; j < DV; j++) acc += w_out[j] * w_v[j * SRC + c];
        g_wvo[c] = acc;
    }
}

// ---------------- kernel 2: Q/K projections ------------------------
// Y[8192,128] = X[8192,768] @ W[128,768]^T.  blockIdx.y: 0 -> Q, 1 -> K.
// BM=64 rows, BN=128 cols, BK=32. 256 threads, 4x8 register tile.
__global__ void __launch_bounds__(256, 2)
proj_kernel(const float* __restrict__ x1, const float* __restrict__ x2,
            const float* __restrict__ wq, const float* __restrict__ wk) {
    const float* X;
    const float* W;
    float* Y;
    if (blockIdx.y == 0) { X = x1; W = wq; Y = g_Q; }
    else                 { X = x2; W = wk; Y = g_K; }

    __shared__ float Xs[32][68];   // [k][row], pad 68 so float4 loads stay 16B-aligned
    __shared__ float Ws[32][129];  // [k][col]

    const int tid = threadIdx.x;
    const int tx = tid & 15;       // column group: col = tx + 16j
    const int ty = tid >> 4;       // row group:    row = 4ty + i
    const int r0 = blockIdx.x * 64;

    float acc[4][8];
    #pragma unroll
    for (int i = 0; i < 4; i++)
        #pragma unroll
        for (int j = 0; j < 8; j++) acc[i][j] = 0.0f;

    for (int kk = 0; kk < SRC; kk += 32) {
        // X tile: 64 rows x 32 k
        #pragma unroll
        for (int i = 0; i < 2; i++) {
            int idx = tid + i * 256;
            int row = idx >> 3, kv = idx & 7;
            float4 v = *reinterpret_cast<const float4*>(&X[(r0 + row) * SRC + kk + kv * 4]);
            Xs[4 * kv + 0][row] = v.x;
            Xs[4 * kv + 1][row] = v.y;
            Xs[4 * kv + 2][row] = v.z;
            Xs[4 * kv + 3][row] = v.w;
        }
        // W tile: 128 cols x 32 k
        #pragma unroll
        for (int i = 0; i < 4; i++) {
            int idx = tid + i * 256;
            int col = idx >> 3, kv = idx & 7;
            float4 v = *reinterpret_cast<const float4*>(&W[col * SRC + kk + kv * 4]);
            Ws[4 * kv + 0][col] = v.x;
            Ws[4 * kv + 1][col] = v.y;
            Ws[4 * kv + 2][col] = v.z;
            Ws[4 * kv + 3][col] = v.w;
        }
        __syncthreads();

        #pragma unroll
        for (int k = 0; k < 32; k++) {
            float4 xv = *reinterpret_cast<const float4*>(&Xs[k][4 * ty]);
            float xr[4] = {xv.x, xv.y, xv.z, xv.w};
            float wf[8];
            #pragma unroll
            for (int j = 0; j < 8; j++) wf[j] = Ws[k][tx + 16 * j];
            #pragma unroll
            for (int i = 0; i < 4; i++)
                #pragma unroll
                for (int j = 0; j < 8; j++) acc[i][j] = fmaf(xr[i], wf[j], acc[i][j]);
        }
        __syncthreads();
    }

    #pragma unroll
    for (int i = 0; i < 4; i++)
        #pragma unroll
        for (int j = 0; j < 8; j++)
            Y[(r0 + 4 * ty + i) * DK + tx + 16 * j] = acc[i][j];
}

// ---------------- kernel 3: v_s = x2 @ wvo, plus sum(x2) -----------
__global__ void vscalar_kernel(const float* __restrict__ x2) {
    const int warp = threadIdx.x >> 5, lane = threadIdx.x & 31;
    const int row = blockIdx.x * 8 + warp;
    const float* xr = x2 + (size_t)row * SRC;
    float acc = 0.0f, s = 0.0f;
    #pragma unroll
    for (int c = lane; c < SRC; c += 32) {
        float v = xr[c];
        acc = fmaf(v, g_wvo[c], acc);
        s += v;
    }
    #pragma unroll
    for (int m = 16; m; m >>= 1) {
        acc += __shfl_xor_sync(0xffffffffu, acc, m);
        s   += __shfl_xor_sync(0xffffffffu, s, m);
    }
    if (lane == 0) {
        g_vs[row] = acc;
        atomicAdd(&g_x2sum, s);
    }
}

// ---------------- kernel 4: flash attention with scalar V ----------
// BM=64 queries per CTA, BN=64 keys per iteration, 256 threads,
// 4x4 f32x2 score tile per thread. Scores never touch global memory.
#define FBM 64
#define FBN 64

struct __align__(16) SmemFlash {
    float2 Q2[64][66];   // [k-pair][query row]  (pad 66: even stride -> 16B aligned float4)
    float2 K2[64][66];   // [k-pair][key row]
    float  vsb[FBN];
};

extern __shared__ char smem_raw[];

__global__ void __launch_bounds__(256, 1) flash_kernel() {
    SmemFlash& sm = *reinterpret_cast<SmemFlash*>(smem_raw);
    const int tid = threadIdx.x;
    const int tx = tid & 15;     // key col group:  col = tx + 16j
    const int ty = tid >> 4;     // query row grp:  row = 4ty + i
    const int r0 = blockIdx.x * FBM;

    // Load + transpose Q tile into k-pair-major smem
    #pragma unroll
    for (int i = 0; i < 8; i++) {
        int idx = tid + i * 256;          // 0..2047
        int row = idx >> 5;               // 0..63
        int kv  = idx & 31;               // float4 index along k
        float4 q = *reinterpret_cast<const float4*>(&g_Q[(size_t)(r0 + row) * DK + kv * 4]);
        sm.Q2[2 * kv + 0][row] = make_float2(q.x, q.y);
        sm.Q2[2 * kv + 1][row] = make_float2(q.z, q.w);
    }
    __syncthreads();

    float m[4], l[4], a[4];
    #pragma unroll
    for (int i = 0; i < 4; i++) { m[i] = -CUDART_INF_F; l[i] = 0.0f; a[i] = 0.0f; }

    const float scale = 0.08838834764831845f;  // 1/sqrt(128)

    for (int t0 = 0; t0 < S_N; t0 += FBN) {
        // Load + transpose K tile, load scalar-V slice
        #pragma unroll
        for (int i = 0; i < 8; i++) {
            int idx = tid + i * 256;
            int row = idx >> 5;
            int kv  = idx & 31;
            float4 k = *reinterpret_cast<const float4*>(&g_K[(size_t)(t0 + row) * DK + kv * 4]);
            sm.K2[2 * kv + 0][row] = make_float2(k.x, k.y);
            sm.K2[2 * kv + 1][row] = make_float2(k.z, k.w);
        }
        if (tid < FBN) sm.vsb[tid] = g_vs[t0 + tid];
        __syncthreads();

        // --- QK^T: 4x4 tile per thread, packed f32x2 over the k dim ---
        ull acc[4][4];
        #pragma unroll
        for (int i = 0; i < 4; i++)
            #pragma unroll
            for (int j = 0; j < 4; j++) acc[i][j] = 0ull;

        #pragma unroll 4
        for (int k2 = 0; k2 < 64; k2++) {
            float4 a0 = *reinterpret_cast<const float4*>(&sm.Q2[k2][4 * ty]);
            float4 a1 = *reinterpret_cast<const float4*>(&sm.Q2[k2][4 * ty + 2]);
            ull q[4];
            q[0] = pk2(a0.x, a0.y);
            q[1] = pk2(a0.z, a0.w);
            q[2] = pk2(a1.x, a1.y);
            q[3] = pk2(a1.z, a1.w);
            ull kf[4];
            #pragma unroll
            for (int j = 0; j < 4; j++) {
                float2 kv2 = sm.K2[k2][tx + 16 * j];
                kf[j] = pk2(kv2.x, kv2.y);
            }
            #pragma unroll
            for (int i = 0; i < 4; i++)
                #pragma unroll
                for (int j = 0; j < 4; j++)
                    acc[i][j] = ffma2(q[i], kf[j], acc[i][j]);
        }

        // collapse f32x2 lanes, apply 1/sqrt(dk)
        float s[4][4];
        #pragma unroll
        for (int i = 0; i < 4; i++)
            #pragma unroll
            for (int j = 0; j < 4; j++) {
                float lo, hi;
                upk2(acc[i][j], lo, hi);
                s[i][j] = (lo + hi) * scale;
            }

        // --- online softmax, scalar V.  Reduce over the 16 lanes that
        //     share a query row (lane groups are 16-aligned: xor<16 stays inside)
        #pragma unroll
        for (int i = 0; i < 4; i++) {
            float bm = fmaxf(fmaxf(s[i][0], s[i][1]), fmaxf(s[i][2], s[i][3]));
            #pragma unroll
            for (int msk = 8; msk; msk >>= 1)
                bm = fmaxf(bm, __shfl_xor_sync(0xffffffffu, bm, msk));
            float nm = fmaxf(m[i], bm);
            float corr = __expf(m[i] - nm);
            float sp = 0.0f, spv = 0.0f;
            #pragma unroll
            for (int j = 0; j < 4; j++) {
                float p = __expf(s[i][j] - nm);
                sp += p;
                spv = fmaf(p, sm.vsb[tx + 16 * j], spv);
            }
            #pragma unroll
            for (int msk = 8; msk; msk >>= 1) {
                sp  += __shfl_xor_sync(0xffffffffu, sp, msk);
                spv += __shfl_xor_sync(0xffffffffu, spv, msk);
            }
            l[i] = l[i] * corr + sp;
            a[i] = a[i] * corr + spv;
            m[i] = nm;
        }
        __syncthreads();
    }

    if (tx == 0) {
        #pragma unroll
        for (int i = 0; i < 4; i++)
            g_out[r0 + 4 * ty + i] = a[i] / l[i];
    }
}

// ---------------- kernel 5: y = x1 * (1 - out) (or x1 if sum==0) ---
__global__ void gate_kernel(const float* __restrict__ x1, float* __restrict__ y) {
    int i = blockIdx.x * 256 + threadIdx.x;      // float4 index; 1,572,864 total
    float4 v = reinterpret_cast<const float4*>(x1)[i];
    int row = i / (SRC / 4);
    float g = (g_x2sum == 0.0f) ? 0.0f : g_out[row];
    float f = 1.0f - g;
    v.x *= f; v.y *= f; v.z *= f; v.w *= f;
    reinterpret_cast<float4*>(y)[i] = v;
}

// ---------------- launch ------------------------------------------
extern "C" void kernel_launch(void* const* d_in, const int* in_sizes, int n_in,
                              void* d_out, int out_size) {
    const float* x1 = (const float*)d_in[0];   // [1,8192,768]
    const float* x2 = (const float*)d_in[1];   // [1,8192,768]
    const float* wq = (const float*)d_in[2];   // [128,768]
    const float* wk = (const float*)d_in[3];   // [128,768]
    const float* wv = (const float*)d_in[4];   // [64,768]
    const float* wo = (const float*)d_in[5];   // [1,64]
    float* y = (float*)d_out;

    cudaFuncSetAttribute(flash_kernel, cudaFuncAttributeMaxDynamicSharedMemorySize,
                         (int)sizeof(SmemFlash));

    prep_kernel<<<1, 768>>>(wv, wo);
    proj_kernel<<<dim3(S_N / 64, 2), 256>>>(x1, x2, wq, wk);
    vscalar_kernel<<<S_N / 8, 256>>>(x2);
    flash_kernel<<<S_N / FBM, 256, sizeof(SmemFlash)>>>();
    gate_kernel<<<(S_N * SRC / 4) / 256, 256>>>(x1, y);
}

// round 3
// speedup vs baseline: 4.4393x; 4.4393x over previous
#include <cuda_runtime.h>
#include <cuda_fp16.h>
#include <math_constants.h>

#define S_N   8192
#define SRC   768
#define DK    128
#define DV    64

typedef unsigned long long ull;
typedef unsigned int u32;

// ---------------- scratch (no allocations allowed) ----------------
__device__ __half g_Qf[S_N * DK];   // Q * log2e/sqrt(dk), fp16
__device__ __half g_Kf[S_N * DK];   // K, fp16
__device__ float g_vs[S_N];         // scalar V per key
__device__ float g_pl[2 * S_N], g_pa[2 * S_N];  // key-split partials (additive)
__device__ float g_out[S_N];        // gate scalar per query
__device__ float g_wvo[SRC];        // w_output @ w_v
__device__ float g_x2sum;

// ---------------- helpers ------------------------------------------
__device__ __forceinline__ ull pk2(float x, float y) {
    ull r; asm("mov.b64 %0, {%1, %2};" : "=l"(r) : "f"(x), "f"(y)); return r;
}
__device__ __forceinline__ void upk2(ull v, float& x, float& y) {
    asm("mov.b64 {%0, %1}, %2;" : "=f"(x), "=f"(y) : "l"(v));
}
__device__ __forceinline__ ull ffma2(ull a, ull b, ull c) {
    ull d; asm("fma.rn.f32x2 %0, %1, %2, %3;" : "=l"(d) : "l"(a), "l"(b), "l"(c)); return d;
}
__device__ __forceinline__ float ex2f(float x) {
    float y; asm("ex2.approx.f32 %0, %1;" : "=f"(y) : "f"(x)); return y;
}
__device__ __forceinline__ u32 smem_u32(const void* p) {
    u32 a; asm("{ .reg .u64 t; cvta.to.shared.u64 t, %1; cvt.u32.u64 %0, t; }" : "=r"(a) : "l"(p));
    return a;
}
__device__ __forceinline__ void ldsm_x4(u32& r0, u32& r1, u32& r2, u32& r3, u32 addr) {
    asm volatile("ldmatrix.sync.aligned.m8n8.x4.shared.b16 {%0,%1,%2,%3}, [%4];"
                 : "=r"(r0), "=r"(r1), "=r"(r2), "=r"(r3) : "r"(addr));
}
__device__ __forceinline__ void mma16816(float& d0, float& d1, float& d2, float& d3,
                                         u32 a0, u32 a1, u32 a2, u32 a3,
                                         u32 b0, u32 b1) {
    asm volatile("mma.sync.aligned.m16n8k16.row.col.f32.f16.f16.f32 "
                 "{%0,%1,%2,%3},{%4,%5,%6,%7},{%8,%9},{%0,%1,%2,%3};"
                 : "+f"(d0), "+f"(d1), "+f"(d2), "+f"(d3)
                 : "r"(a0), "r"(a1), "r"(a2), "r"(a3), "r"(b0), "r"(b1));
}

// log2(e) / sqrt(128): folded into Q so softmax uses raw EX2, no max needed
#define CFOLD 0.12751743f

// ---------------- kernel 1: wvo = w_output @ w_v; zero flag --------
__global__ void prep_kernel(const float* __restrict__ w_v,
                            const float* __restrict__ w_out) {
    int c = threadIdx.x;
    if (c == 0) g_x2sum = 0.0f;
    if (c < SRC) {
        float acc = 0.0f;
        #pragma unroll
        for (int j = 0; j < DV; j++) acc += w_out[j] * w_v[j * SRC + c];
        g_wvo[c] = acc;
    }
}

// ---------------- kernel 2: Q/K projections, f32x2, fp16 out -------
// Y[8192,128] = X @ W^T.  BM=128 rows, BN=128 cols, BK=16, 256 threads.
__global__ void __launch_bounds__(256, 1)
proj_kernel(const float* __restrict__ x1, const float* __restrict__ x2,
            const float* __restrict__ wq, const float* __restrict__ wk) {
    const bool isQ = (blockIdx.y == 0);
    const float* X = isQ ? x1 : x2;
    const float* W = isQ ? wq : wk;
    __half* Y = isQ ? g_Qf : g_Kf;

    __shared__ float Xs[16][130];
    __shared__ float Ws[16][130];

    const int tid = threadIdx.x;
    const int tx = tid & 15;
    const int ty = tid >> 4;
    const int r0 = blockIdx.x * 128;

    ull acc[4][8];
    #pragma unroll
    for (int i = 0; i < 4; i++)
        #pragma unroll
        for (int j = 0; j < 8; j++) acc[i][j] = 0ull;

    int row_[2], kq_[2];
    #pragma unroll
    for (int i = 0; i < 2; i++) {
        int idx = tid + i * 256;
        row_[i] = idx >> 2;
        kq_[i]  = idx & 3;
    }
    float4 xr[2], wr[2];
    #pragma unroll
    for (int i = 0; i < 2; i++) {
        xr[i] = *reinterpret_cast<const float4*>(&X[(size_t)(r0 + row_[i]) * SRC + kq_[i] * 4]);
        wr[i] = *reinterpret_cast<const float4*>(&W[(size_t)row_[i] * SRC + kq_[i] * 4]);
    }

    for (int kk = 0; kk < SRC; kk += 16) {
        #pragma unroll
        for (int i = 0; i < 2; i++) {
            Xs[kq_[i] * 4 + 0][row_[i]] = xr[i].x;
            Xs[kq_[i] * 4 + 1][row_[i]] = xr[i].y;
            Xs[kq_[i] * 4 + 2][row_[i]] = xr[i].z;
            Xs[kq_[i] * 4 + 3][row_[i]] = xr[i].w;
            Ws[kq_[i] * 4 + 0][row_[i]] = wr[i].x;
            Ws[kq_[i] * 4 + 1][row_[i]] = wr[i].y;
            Ws[kq_[i] * 4 + 2][row_[i]] = wr[i].z;
            Ws[kq_[i] * 4 + 3][row_[i]] = wr[i].w;
        }
        __syncthreads();
        if (kk + 16 < SRC) {
            #pragma unroll
            for (int i = 0; i < 2; i++) {
                xr[i] = *reinterpret_cast<const float4*>(&X[(size_t)(r0 + row_[i]) * SRC + kk + 16 + kq_[i] * 4]);
                wr[i] = *reinterpret_cast<const float4*>(&W[(size_t)row_[i] * SRC + kk + 16 + kq_[i] * 4]);
            }
        }
        #pragma unroll
        for (int k = 0; k < 16; k++) {
            ull xp[4], wp[8];
            #pragma unroll
            for (int i = 0; i < 4; i++)
                xp[i] = *reinterpret_cast<const ull*>(&Xs[k][8 * ty + 2 * i]);
            #pragma unroll
            for (int j = 0; j < 8; j++) {
                float wv = Ws[k][tx + 16 * j];
                wp[j] = pk2(wv, wv);
            }
            #pragma unroll
            for (int i = 0; i < 4; i++)
                #pragma unroll
                for (int j = 0; j < 8; j++)
                    acc[i][j] = ffma2(xp[i], wp[j], acc[i][j]);
        }
        __syncthreads();
    }

    #pragma unroll
    for (int i = 0; i < 4; i++) {
        #pragma unroll
        for (int j = 0; j < 8; j++) {
            float v0, v1;
            upk2(acc[i][j], v0, v1);
            if (isQ) { v0 *= CFOLD; v1 *= CFOLD; }
            int col = tx + 16 * j;
            size_t o0 = (size_t)(r0 + 8 * ty + 2 * i) * DK + col;
            Y[o0]      = __float2half_rn(v0);
            Y[o0 + DK] = __float2half_rn(v1);
        }
    }
}

// ---------------- kernel 3: v_s = x2 @ wvo, plus sum(x2) -----------
__global__ void vscalar_kernel(const float* __restrict__ x2) {
    const int warp = threadIdx.x >> 5, lane = threadIdx.x & 31;
    const int row = blockIdx.x * 8 + warp;
    const float* xr = x2 + (size_t)row * SRC;
    float acc = 0.0f, s = 0.0f;
    #pragma unroll
    for (int c = lane; c < SRC; c += 32) {
        float v = xr[c];
        acc = fmaf(v, g_wvo[c], acc);
        s += v;
    }
    #pragma unroll
    for (int m = 16; m; m >>= 1) {
        acc += __shfl_xor_sync(0xffffffffu, acc, m);
        s   += __shfl_xor_sync(0xffffffffu, s, m);
    }
    if (lane == 0) {
        g_vs[row] = acc;
        atomicAdd(&g_x2sum, s);
    }
}

// ---------------- kernel 4: HMMA flash attention (scalar V) --------
// CTA: 128 queries x 64-key tiles, 8 warps (warp = 32q x 32k).
// grid (64, 2): blockIdx.y key-split. No max tracking (scores tiny, p=2^s).
#define OFF_KS   32768         /* __half Ks[2][64][128] */
#define OFF_VSB  65536         /* float vsb[2][64] */
#define OFF_RL   66048         /* float rl[2][128] */
#define OFF_RA   68096         /* float ra[2][128] */
#define SMEM_FLASH 69120

extern __shared__ char smem_raw[];

__global__ void __launch_bounds__(256, 1) flash_kernel() {
    __half* Qs = reinterpret_cast<__half*>(smem_raw);
    float* vsb = reinterpret_cast<float*>(smem_raw + OFF_VSB);
    float* rl  = reinterpret_cast<float*>(smem_raw + OFF_RL);
    float* ra  = reinterpret_cast<float*>(smem_raw + OFF_RA);

    const int tid = threadIdx.x, lane = tid & 31, w = tid >> 5;
    const int q0 = blockIdx.x * 128;
    const int k0 = blockIdx.y * 4096;
    const int kh = w >> 2;       // key half within tile (0/1)
    const int qg = w & 3;        // 32-query group

    // stage Q (XOR-swizzled: phys chunk = chunk ^ (row&7))
    #pragma unroll
    for (int i = 0; i < 8; i++) {
        int idx = tid + i * 256;
        int row = idx >> 4, ch = idx & 15;
        u32 dst = (u32)(row * 256) + (u32)((ch ^ (row & 7)) << 4);
        *reinterpret_cast<uint4*>(smem_raw + dst) =
            *reinterpret_cast<const uint4*>(g_Qf + (size_t)(q0 + row) * DK + ch * 8);
    }
    // stage K tile 0 + vs 0
    #pragma unroll
    for (int i = 0; i < 4; i++) {
        int idx = tid + i * 256;
        int row = idx >> 4, ch = idx & 15;
        u32 dst = (u32)(row * 256) + (u32)((ch ^ (row & 7)) << 4);
        *reinterpret_cast<uint4*>(smem_raw + OFF_KS + dst) =
            *reinterpret_cast<const uint4*>(g_Kf + (size_t)(k0 + row) * DK + ch * 8);
    }
    if (tid < 64) vsb[tid] = g_vs[k0 + tid];
    __syncthreads();

    // A fragments: register-resident for the whole CTA lifetime
    u32 A[2][8][4];
    {
        const u32 sQ = smem_u32(Qs);
        int rb = qg * 32 + (lane & 7) + (lane & 8);
        int kbit = lane >> 4;
        #pragma unroll
        for (int mt = 0; mt < 2; mt++) {
            int row = rb + mt * 16;
            #pragma unroll
            for (int ks = 0; ks < 8; ks++) {
                int ch = ks * 2 + kbit;
                u32 addr = sQ + row * 256 + ((ch ^ (row & 7)) << 4);
                ldsm_x4(A[mt][ks][0], A[mt][ks][1], A[mt][ks][2], A[mt][ks][3], addr);
            }
        }
    }

    const u32 sK = smem_u32(smem_raw + OFF_KS);
    const int rB0 = kh * 32 + (lane & 7) + ((lane & 16) >> 1);  // jj=0 rows
    const int kbitB = (lane >> 3) & 1;

    float l_[4] = {0, 0, 0, 0}, a_[4] = {0, 0, 0, 0};

    for (int it = 0; it < 64; it++) {
        const int buf = it & 1;
        // prefetch next K tile into regs
        uint4 pf[4];
        float pvs = 0.0f;
        if (it + 1 < 64) {
            int t0 = k0 + (it + 1) * 64;
            #pragma unroll
            for (int i = 0; i < 4; i++) {
                int idx = tid + i * 256;
                int row = idx >> 4, ch = idx & 15;
                pf[i] = *reinterpret_cast<const uint4*>(g_Kf + (size_t)(t0 + row) * DK + ch * 8);
            }
            if (tid < 64) pvs = g_vs[t0 + tid];
        }

        // ---- QK^T on tensor cores ----
        float c[2][4][4];
        #pragma unroll
        for (int mt = 0; mt < 2; mt++)
            #pragma unroll
            for (int j = 0; j < 4; j++)
                #pragma unroll
                for (int e = 0; e < 4; e++) c[mt][j][e] = 0.0f;

        const u32 kb = sK + buf * 16384;
        #pragma unroll
        for (int ks = 0; ks < 8; ks++) {
            u32 b[8];
            int ch = ks * 2 + kbitB;
            {
                int row = rB0;
                ldsm_x4(b[0], b[1], b[2], b[3],
                        kb + row * 256 + ((ch ^ (row & 7)) << 4));
            }
            {
                int row = rB0 + 16;
                ldsm_x4(b[4], b[5], b[6], b[7],
                        kb + row * 256 + ((ch ^ (row & 7)) << 4));
            }
            #pragma unroll
            for (int mt = 0; mt < 2; mt++) {
                mma16816(c[mt][0][0], c[mt][0][1], c[mt][0][2], c[mt][0][3],
                         A[mt][ks][0], A[mt][ks][1], A[mt][ks][2], A[mt][ks][3], b[0], b[1]);
                mma16816(c[mt][1][0], c[mt][1][1], c[mt][1][2], c[mt][1][3],
                         A[mt][ks][0], A[mt][ks][1], A[mt][ks][2], A[mt][ks][3], b[2], b[3]);
                mma16816(c[mt][2][0], c[mt][2][1], c[mt][2][2], c[mt][2][3],
                         A[mt][ks][0], A[mt][ks][1], A[mt][ks][2], A[mt][ks][3], b[4], b[5]);
                mma16816(c[mt][3][0], c[mt][3][1], c[mt][3][2], c[mt][3][3],
                         A[mt][ks][0], A[mt][ks][1], A[mt][ks][2], A[mt][ks][3], b[6], b[7]);
            }
        }

        // ---- softmax accumulate (no max: p = 2^s, scores are small) ----
        const float* vv = vsb + buf * 64 + kh * 32 + (lane & 3) * 2;
        #pragma unroll
        for (int j = 0; j < 4; j++) {
            float2 vs2 = *reinterpret_cast<const float2*>(vv + j * 8);
            #pragma unroll
            for (int mt = 0; mt < 2; mt++) {
                float p0 = ex2f(c[mt][j][0]);
                float p1 = ex2f(c[mt][j][1]);
                float p2 = ex2f(c[mt][j][2]);
                float p3 = ex2f(c[mt][j][3]);
                l_[mt * 2 + 0] += p0 + p1;
                l_[mt * 2 + 1] += p2 + p3;
                a_[mt * 2 + 0] = fmaf(p0, vs2.x, fmaf(p1, vs2.y, a_[mt * 2 + 0]));
                a_[mt * 2 + 1] = fmaf(p2, vs2.x, fmaf(p3, vs2.y, a_[mt * 2 + 1]));
            }
        }

        // store next tile into the other buffer
        if (it + 1 < 64) {
            char* kd = smem_raw + OFF_KS + (1 - buf) * 16384;
            #pragma unroll
            for (int i = 0; i < 4; i++) {
                int idx = tid + i * 256;
                int row = idx >> 4, ch = idx & 15;
                u32 dst = (u32)(row * 256) + (u32)((ch ^ (row & 7)) << 4);
                *reinterpret_cast<uint4*>(kd + dst) = pf[i];
            }
            if (tid < 64) vsb[(1 - buf) * 64 + tid] = pvs;
        }
        __syncthreads();
    }

    // quad reduce (lanes sharing a row are lane^1, lane^2)
    #pragma unroll
    for (int r = 0; r < 4; r++) {
        l_[r] += __shfl_xor_sync(0xffffffffu, l_[r], 1);
        l_[r] += __shfl_xor_sync(0xffffffffu, l_[r], 2);
        a_[r] += __shfl_xor_sync(0xffffffffu, a_[r], 1);
        a_[r] += __shfl_xor_sync(0xffffffffu, a_[r], 2);
    }
    if ((lane & 3) == 0) {
        int gid = lane >> 2;
        #pragma unroll
        for (int r = 0; r < 4; r++) {
            int mt = r >> 1, hi = r & 1;
            int qrow = qg * 32 + mt * 16 + gid + hi * 8;
            rl[kh * 128 + qrow] = l_[r];
            ra[kh * 128 + qrow] = a_[r];
        }
    }
    __syncthreads();
    if (tid < 128) {
        int r = blockIdx.y * S_N + q0 + tid;
        g_pl[r] = rl[tid] + rl[128 + tid];
        g_pa[r] = ra[tid] + ra[128 + tid];
    }
}

// ---------------- kernel 5: combine key-splits ---------------------
__global__ void combine2_kernel() {
    int r = blockIdx.x * 256 + threadIdx.x;
    float L = g_pl[r] + g_pl[S_N + r];
    float A = g_pa[r] + g_pa[S_N + r];
    g_out[r] = A / L;
}

// ---------------- kernel 6: y = x1 * (1 - out) (or x1 if sum==0) ---
__global__ void gate_kernel(const float* __restrict__ x1, float* __restrict__ y) {
    int i = blockIdx.x * 256 + threadIdx.x;
    float4 v = reinterpret_cast<const float4*>(x1)[i];
    int row = i / (SRC / 4);
    float g = (g_x2sum == 0.0f) ? 0.0f : g_out[row];
    float f = 1.0f - g;
    v.x *= f; v.y *= f; v.z *= f; v.w *= f;
    reinterpret_cast<float4*>(y)[i] = v;
}

// ---------------- launch ------------------------------------------
extern "C" void kernel_launch(void* const* d_in, const int* in_sizes, int n_in,
                              void* d_out, int out_size) {
    const float* x1 = (const float*)d_in[0];
    const float* x2 = (const float*)d_in[1];
    const float* wq = (const float*)d_in[2];
    const float* wk = (const float*)d_in[3];
    const float* wv = (const float*)d_in[4];
    const float* wo = (const float*)d_in[5];
    float* y = (float*)d_out;

    cudaFuncSetAttribute(flash_kernel, cudaFuncAttributeMaxDynamicSharedMemorySize,
                         SMEM_FLASH);

    prep_kernel<<<1, 768>>>(wv, wo);
    proj_kernel<<<dim3(S_N / 128, 2), 256>>>(x1, x2, wq, wk);
    vscalar_kernel<<<S_N / 8, 256>>>(x2);
    flash_kernel<<<dim3(S_N / 128, 2), 256, SMEM_FLASH>>>();
    combine2_kernel<<<S_N / 256, 256>>>();
    gate_kernel<<<(S_N * SRC / 4) / 256, 256>>>(x1, y);
}

// round 4
// speedup vs baseline: 6.6356x; 1.4947x over previous
#include <cuda_runtime.h>
#include <cuda_fp16.h>
#include <math_constants.h>

#define S_N   8192
#define SRC   768
#define DK    128
#define DV    64

typedef unsigned long long ull;
typedef unsigned int u32;

// ---------------- scratch (no allocations allowed) ----------------
__device__ __half g_Qf[S_N * DK];   // Q * log2e/sqrt(dk), fp16
__device__ __half g_Kf[S_N * DK];   // K, fp16
__device__ float g_vs[S_N];         // scalar V per key
__device__ float g_pl[2 * S_N], g_pa[2 * S_N];  // key-split partials (additive)
__device__ float g_out[S_N];        // gate scalar per query
__device__ float g_wvo[SRC];        // w_output @ w_v
__device__ float g_x2sum;

// ---------------- helpers ------------------------------------------
__device__ __forceinline__ float ex2f(float x) {
    float y; asm("ex2.approx.f32 %0, %1;" : "=f"(y) : "f"(x)); return y;
}
__device__ __forceinline__ u32 smem_u32(const void* p) {
    u32 a; asm("{ .reg .u64 t; cvta.to.shared.u64 t, %1; cvt.u32.u64 %0, t; }" : "=r"(a) : "l"(p));
    return a;
}
__device__ __forceinline__ void ldsm_x4(u32& r0, u32& r1, u32& r2, u32& r3, u32 addr) {
    asm volatile("ldmatrix.sync.aligned.m8n8.x4.shared.b16 {%0,%1,%2,%3}, [%4];"
                 : "=r"(r0), "=r"(r1), "=r"(r2), "=r"(r3) : "r"(addr));
}
__device__ __forceinline__ void mma16816(float& d0, float& d1, float& d2, float& d3,
                                         u32 a0, u32 a1, u32 a2, u32 a3,
                                         u32 b0, u32 b1) {
    asm volatile("mma.sync.aligned.m16n8k16.row.col.f32.f16.f16.f32 "
                 "{%0,%1,%2,%3},{%4,%5,%6,%7},{%8,%9},{%0,%1,%2,%3};"
                 : "+f"(d0), "+f"(d1), "+f"(d2), "+f"(d3)
                 : "r"(a0), "r"(a1), "r"(a2), "r"(a3), "r"(b0), "r"(b1));
}
__device__ __forceinline__ uint4 cvt8h(float4 a, float4 b) {
    __half2 h0 = __floats2half2_rn(a.x, a.y);
    __half2 h1 = __floats2half2_rn(a.z, a.w);
    __half2 h2 = __floats2half2_rn(b.x, b.y);
    __half2 h3 = __floats2half2_rn(b.z, b.w);
    uint4 u;
    u.x = *reinterpret_cast<u32*>(&h0);
    u.y = *reinterpret_cast<u32*>(&h1);
    u.z = *reinterpret_cast<u32*>(&h2);
    u.w = *reinterpret_cast<u32*>(&h3);
    return u;
}

// log2(e) / sqrt(128): folded into Q so softmax uses raw EX2, no max needed
#define CFOLD 0.12751743f

extern __shared__ char smem_raw[];

// ---------------- kernel 1: wvo = w_output @ w_v; zero flag --------
__global__ void prep_kernel(const float* __restrict__ w_v,
                            const float* __restrict__ w_out) {
    int c = threadIdx.x;
    if (c == 0) g_x2sum = 0.0f;
    if (c < SRC) {
        float acc = 0.0f;
        #pragma unroll
        for (int j = 0; j < DV; j++) acc += w_out[j] * w_v[j * SRC + c];
        g_wvo[c] = acc;
    }
}

// ---------------- kernel 2: Q/K projections on HMMA ----------------
// Y[8192,128] = X[8192,768] @ W[128,768]^T, fp16 out (Q pre-scaled).
// CTA: 128 rows x 128 cols, K chunks of 64, 512 threads (16 warps,
// warp = 32 rows x 32 cols). fp32->fp16 conversion fused into staging.
#define PCH   12              /* 768 / 64 chunks */
#define SMEM_PROJ 65536       /* Xs[2][128][64]h + Ws[2][128][64]h */

__global__ void __launch_bounds__(512, 1)
proj_kernel(const float* __restrict__ x1, const float* __restrict__ x2,
            const float* __restrict__ wq, const float* __restrict__ wk) {
    const bool isQ = (blockIdx.y == 0);
    const float* X = isQ ? x1 : x2;
    const float* W = isQ ? wq : wk;
    __half* Y = isQ ? g_Qf : g_Kf;

    const int tid = threadIdx.x, lane = tid & 31, w = tid >> 5;
    const int qg = w & 3;         // 32-row group
    const int nh = w >> 2;        // 32-col group
    const int r0 = blockIdx.x * 128;

    // staging map: 1024 uint4 slots per matrix per chunk (128 rows x 8 ch)
    int srow[2], sch[2];
    #pragma unroll
    for (int i = 0; i < 2; i++) {
        int idx = tid + i * 512;
        srow[i] = idx >> 3;
        sch[i]  = idx & 7;
    }

    uint4 pX[2], pW[2];
    auto load_regs = [&](int kk) {
        #pragma unroll
        for (int i = 0; i < 2; i++) {
            const float* sx = &X[(size_t)(r0 + srow[i]) * SRC + kk + sch[i] * 8];
            pX[i] = cvt8h(*reinterpret_cast<const float4*>(sx),
                          *reinterpret_cast<const float4*>(sx + 4));
            const float* sw = &W[(size_t)srow[i] * SRC + kk + sch[i] * 8];
            pW[i] = cvt8h(*reinterpret_cast<const float4*>(sw),
                          *reinterpret_cast<const float4*>(sw + 4));
        }
    };
    auto store_smem = [&](int buf) {
        char* xb = smem_raw + buf * 16384;
        char* wb = smem_raw + 32768 + buf * 16384;
        #pragma unroll
        for (int i = 0; i < 2; i++) {
            u32 dst = (u32)(srow[i] * 128) + (u32)((sch[i] ^ (srow[i] & 7)) << 4);
            *reinterpret_cast<uint4*>(xb + dst) = pX[i];
            *reinterpret_cast<uint4*>(wb + dst) = pW[i];
        }
    };

    float c[2][4][4];
    #pragma unroll
    for (int mt = 0; mt < 2; mt++)
        #pragma unroll
        for (int j = 0; j < 4; j++)
            #pragma unroll
            for (int e = 0; e < 4; e++) c[mt][j][e] = 0.0f;

    const u32 sX = smem_u32(smem_raw);
    const u32 sW = smem_u32(smem_raw) + 32768;
    const int rbA = qg * 32 + (lane & 7) + (lane & 8);
    const int kbitA = lane >> 4;
    const int rbB = nh * 32 + (lane & 7) + ((lane & 16) >> 1);
    const int kbitB = (lane >> 3) & 1;

    load_regs(0);
    for (int cidx = 0; cidx < PCH; cidx++) {
        const int buf = cidx & 1;
        store_smem(buf);
        __syncthreads();
        if (cidx + 1 < PCH) load_regs((cidx + 1) * 64);

        const u32 xb = sX + buf * 16384;
        const u32 wb = sW + buf * 16384;
        #pragma unroll
        for (int ks = 0; ks < 4; ks++) {
            u32 A0[4], A1[4];
            int chA = ks * 2 + kbitA;
            {
                int r = rbA;
                ldsm_x4(A0[0], A0[1], A0[2], A0[3], xb + r * 128 + ((chA ^ (r & 7)) << 4));
            }
            {
                int r = rbA + 16;
                ldsm_x4(A1[0], A1[1], A1[2], A1[3], xb + r * 128 + ((chA ^ (r & 7)) << 4));
            }
            int chB = ks * 2 + kbitB;
            #pragma unroll
            for (int nt = 0; nt < 2; nt++) {
                u32 b[4];
                int r = rbB + nt * 16;
                ldsm_x4(b[0], b[1], b[2], b[3], wb + r * 128 + ((chB ^ (r & 7)) << 4));
                mma16816(c[0][nt*2+0][0], c[0][nt*2+0][1], c[0][nt*2+0][2], c[0][nt*2+0][3],
                         A0[0], A0[1], A0[2], A0[3], b[0], b[1]);
                mma16816(c[0][nt*2+1][0], c[0][nt*2+1][1], c[0][nt*2+1][2], c[0][nt*2+1][3],
                         A0[0], A0[1], A0[2], A0[3], b[2], b[3]);
                mma16816(c[1][nt*2+0][0], c[1][nt*2+0][1], c[1][nt*2+0][2], c[1][nt*2+0][3],
                         A1[0], A1[1], A1[2], A1[3], b[0], b[1]);
                mma16816(c[1][nt*2+1][0], c[1][nt*2+1][1], c[1][nt*2+1][2], c[1][nt*2+1][3],
                         A1[0], A1[1], A1[2], A1[3], b[2], b[3]);
            }
        }
        __syncthreads();
    }

    const float scale = isQ ? CFOLD : 1.0f;
    #pragma unroll
    for (int mt = 0; mt < 2; mt++) {
        int row = r0 + qg * 32 + mt * 16 + (lane >> 2);
        #pragma unroll
        for (int j = 0; j < 4; j++) {
            int col = nh * 32 + j * 8 + (lane & 3) * 2;
            __half2 lo = __floats2half2_rn(c[mt][j][0] * scale, c[mt][j][1] * scale);
            __half2 hi = __floats2half2_rn(c[mt][j][2] * scale, c[mt][j][3] * scale);
            *reinterpret_cast<__half2*>(&Y[(size_t)row * DK + col]) = lo;
            *reinterpret_cast<__half2*>(&Y[(size_t)(row + 8) * DK + col]) = hi;
        }
    }
}

// ---------------- kernel 3: v_s = x2 @ wvo, plus sum(x2) -----------
__global__ void vscalar_kernel(const float* __restrict__ x2) {
    const int warp = threadIdx.x >> 5, lane = threadIdx.x & 31;
    const int row = blockIdx.x * 8 + warp;
    const float* xr = x2 + (size_t)row * SRC;
    float acc = 0.0f, s = 0.0f;
    #pragma unroll
    for (int c = lane; c < SRC; c += 32) {
        float v = xr[c];
        acc = fmaf(v, g_wvo[c], acc);
        s += v;
    }
    #pragma unroll
    for (int m = 16; m; m >>= 1) {
        acc += __shfl_xor_sync(0xffffffffu, acc, m);
        s   += __shfl_xor_sync(0xffffffffu, s, m);
    }
    if (lane == 0) {
        g_vs[row] = acc;
        atomicAdd(&g_x2sum, s);
    }
}

// ---------------- kernel 4: HMMA flash attention (scalar V) --------
// CTA: 128 queries x 64-key tiles, 8 warps (warp = 32q x 32k).
// grid (64, 2): blockIdx.y key-split. No max tracking (scores tiny, p=2^s).
#define OFF_KS   32768         /* __half Ks[2][64][128] */
#define OFF_VSB  65536         /* float vsb[2][64] */
#define OFF_RL   66048         /* float rl[2][128] */
#define OFF_RA   68096         /* float ra[2][128] */
#define SMEM_FLASH 69120

__global__ void __launch_bounds__(256, 1) flash_kernel() {
    __half* Qs = reinterpret_cast<__half*>(smem_raw);
    float* vsb = reinterpret_cast<float*>(smem_raw + OFF_VSB);
    float* rl  = reinterpret_cast<float*>(smem_raw + OFF_RL);
    float* ra  = reinterpret_cast<float*>(smem_raw + OFF_RA);

    const int tid = threadIdx.x, lane = tid & 31, w = tid >> 5;
    const int q0 = blockIdx.x * 128;
    const int k0 = blockIdx.y * 4096;
    const int kh = w >> 2;       // key half within tile (0/1)
    const int qg = w & 3;        // 32-query group

    // stage Q (XOR-swizzled: phys chunk = chunk ^ (row&7))
    #pragma unroll
    for (int i = 0; i < 8; i++) {
        int idx = tid + i * 256;
        int row = idx >> 4, ch = idx & 15;
        u32 dst = (u32)(row * 256) + (u32)((ch ^ (row & 7)) << 4);
        *reinterpret_cast<uint4*>(smem_raw + dst) =
            *reinterpret_cast<const uint4*>(g_Qf + (size_t)(q0 + row) * DK + ch * 8);
    }
    // stage K tile 0 + vs 0
    #pragma unroll
    for (int i = 0; i < 4; i++) {
        int idx = tid + i * 256;
        int row = idx >> 4, ch = idx & 15;
        u32 dst = (u32)(row * 256) + (u32)((ch ^ (row & 7)) << 4);
        *reinterpret_cast<uint4*>(smem_raw + OFF_KS + dst) =
            *reinterpret_cast<const uint4*>(g_Kf + (size_t)(k0 + row) * DK + ch * 8);
    }
    if (tid < 64) vsb[tid] = g_vs[k0 + tid];
    __syncthreads();

    // A fragments: register-resident for the whole CTA lifetime
    u32 A[2][8][4];
    {
        const u32 sQ = smem_u32(Qs);
        int rb = qg * 32 + (lane & 7) + (lane & 8);
        int kbit = lane >> 4;
        #pragma unroll
        for (int mt = 0; mt < 2; mt++) {
            int row = rb + mt * 16;
            #pragma unroll
            for (int ks = 0; ks < 8; ks++) {
                int ch = ks * 2 + kbit;
                u32 addr = sQ + row * 256 + ((ch ^ (row & 7)) << 4);
                ldsm_x4(A[mt][ks][0], A[mt][ks][1], A[mt][ks][2], A[mt][ks][3], addr);
            }
        }
    }

    const u32 sK = smem_u32(smem_raw + OFF_KS);
    const int rB0 = kh * 32 + (lane & 7) + ((lane & 16) >> 1);  // jj=0 rows
    const int kbitB = (lane >> 3) & 1;

    float l_[4] = {0, 0, 0, 0}, a_[4] = {0, 0, 0, 0};

    for (int it = 0; it < 64; it++) {
        const int buf = it & 1;
        // prefetch next K tile into regs
        uint4 pf[4];
        float pvs = 0.0f;
        if (it + 1 < 64) {
            int t0 = k0 + (it + 1) * 64;
            #pragma unroll
            for (int i = 0; i < 4; i++) {
                int idx = tid + i * 256;
                int row = idx >> 4, ch = idx & 15;
                pf[i] = *reinterpret_cast<const uint4*>(g_Kf + (size_t)(t0 + row) * DK + ch * 8);
            }
            if (tid < 64) pvs = g_vs[t0 + tid];
        }

        // ---- QK^T on tensor cores ----
        float c[2][4][4];
        #pragma unroll
        for (int mt = 0; mt < 2; mt++)
            #pragma unroll
            for (int j = 0; j < 4; j++)
                #pragma unroll
                for (int e = 0; e < 4; e++) c[mt][j][e] = 0.0f;

        const u32 kb = sK + buf * 16384;
        #pragma unroll
        for (int ks = 0; ks < 8; ks++) {
            u32 b[8];
            int ch = ks * 2 + kbitB;
            {
                int row = rB0;
                ldsm_x4(b[0], b[1], b[2], b[3],
                        kb + row * 256 + ((ch ^ (row & 7)) << 4));
            }
            {
                int row = rB0 + 16;
                ldsm_x4(b[4], b[5], b[6], b[7],
                        kb + row * 256 + ((ch ^ (row & 7)) << 4));
            }
            #pragma unroll
            for (int mt = 0; mt < 2; mt++) {
                mma16816(c[mt][0][0], c[mt][0][1], c[mt][0][2], c[mt][0][3],
                         A[mt][ks][0], A[mt][ks][1], A[mt][ks][2], A[mt][ks][3], b[0], b[1]);
                mma16816(c[mt][1][0], c[mt][1][1], c[mt][1][2], c[mt][1][3],
                         A[mt][ks][0], A[mt][ks][1], A[mt][ks][2], A[mt][ks][3], b[2], b[3]);
                mma16816(c[mt][2][0], c[mt][2][1], c[mt][2][2], c[mt][2][3],
                         A[mt][ks][0], A[mt][ks][1], A[mt][ks][2], A[mt][ks][3], b[4], b[5]);
                mma16816(c[mt][3][0], c[mt][3][1], c[mt][3][2], c[mt][3][3],
                         A[mt][ks][0], A[mt][ks][1], A[mt][ks][2], A[mt][ks][3], b[6], b[7]);
            }
        }

        // ---- softmax accumulate (no max: p = 2^s, scores are small) ----
        const float* vv = vsb + buf * 64 + kh * 32 + (lane & 3) * 2;
        #pragma unroll
        for (int j = 0; j < 4; j++) {
            float2 vs2 = *reinterpret_cast<const float2*>(vv + j * 8);
            #pragma unroll
            for (int mt = 0; mt < 2; mt++) {
                float p0 = ex2f(c[mt][j][0]);
                float p1 = ex2f(c[mt][j][1]);
                float p2 = ex2f(c[mt][j][2]);
                float p3 = ex2f(c[mt][j][3]);
                l_[mt * 2 + 0] += p0 + p1;
                l_[mt * 2 + 1] += p2 + p3;
                a_[mt * 2 + 0] = fmaf(p0, vs2.x, fmaf(p1, vs2.y, a_[mt * 2 + 0]));
                a_[mt * 2 + 1] = fmaf(p2, vs2.x, fmaf(p3, vs2.y, a_[mt * 2 + 1]));
            }
        }

        // store next tile into the other buffer
        if (it + 1 < 64) {
            char* kd = smem_raw + OFF_KS + (1 - buf) * 16384;
            #pragma unroll
            for (int i = 0; i < 4; i++) {
                int idx = tid + i * 256;
                int row = idx >> 4, ch = idx & 15;
                u32 dst = (u32)(row * 256) + (u32)((ch ^ (row & 7)) << 4);
                *reinterpret_cast<uint4*>(kd + dst) = pf[i];
            }
            if (tid < 64) vsb[(1 - buf) * 64 + tid] = pvs;
        }
        __syncthreads();
    }

    // quad reduce (lanes sharing a row are lane^1, lane^2)
    #pragma unroll
    for (int r = 0; r < 4; r++) {
        l_[r] += __shfl_xor_sync(0xffffffffu, l_[r], 1);
        l_[r] += __shfl_xor_sync(0xffffffffu, l_[r], 2);
        a_[r] += __shfl_xor_sync(0xffffffffu, a_[r], 1);
        a_[r] += __shfl_xor_sync(0xffffffffu, a_[r], 2);
    }
    if ((lane & 3) == 0) {
        int gid = lane >> 2;
        #pragma unroll
        for (int r = 0; r < 4; r++) {
            int mt = r >> 1, hi = r & 1;
            int qrow = qg * 32 + mt * 16 + gid + hi * 8;
            rl[kh * 128 + qrow] = l_[r];
            ra[kh * 128 + qrow] = a_[r];
        }
    }
    __syncthreads();
    if (tid < 128) {
        int r = blockIdx.y * S_N + q0 + tid;
        g_pl[r] = rl[tid] + rl[128 + tid];
        g_pa[r] = ra[tid] + ra[128 + tid];
    }
}

// ---------------- kernel 5: combine key-splits ---------------------
__global__ void combine2_kernel() {
    int r = blockIdx.x * 256 + threadIdx.x;
    float L = g_pl[r] + g_pl[S_N + r];
    float A = g_pa[r] + g_pa[S_N + r];
    g_out[r] = A / L;
}

// ---------------- kernel 6: y = x1 * (1 - out) (or x1 if sum==0) ---
__global__ void gate_kernel(const float* __restrict__ x1, float* __restrict__ y) {
    int i = blockIdx.x * 256 + threadIdx.x;
    float4 v = reinterpret_cast<const float4*>(x1)[i];
    int row = i / (SRC / 4);
    float g = (g_x2sum == 0.0f) ? 0.0f : g_out[row];
    float f = 1.0f - g;
    v.x *= f; v.y *= f; v.z *= f; v.w *= f;
    reinterpret_cast<float4*>(y)[i] = v;
}

// ---------------- launch ------------------------------------------
extern "C" void kernel_launch(void* const* d_in, const int* in_sizes, int n_in,
                              void* d_out, int out_size) {
    const float* x1 = (const float*)d_in[0];
    const float* x2 = (const float*)d_in[1];
    const float* wq = (const float*)d_in[2];
    const float* wk = (const float*)d_in[3];
    const float* wv = (const float*)d_in[4];
    const float* wo = (const float*)d_in[5];
    float* y = (float*)d_out;

    cudaFuncSetAttribute(flash_kernel, cudaFuncAttributeMaxDynamicSharedMemorySize,
                         SMEM_FLASH);
    cudaFuncSetAttribute(proj_kernel, cudaFuncAttributeMaxDynamicSharedMemorySize,
                         SMEM_PROJ);

    prep_kernel<<<1, 768>>>(wv, wo);
    proj_kernel<<<dim3(S_N / 128, 2), 512, SMEM_PROJ>>>(x1, x2, wq, wk);
    vscalar_kernel<<<S_N / 8, 256>>>(x2);
    flash_kernel<<<dim3(S_N / 128, 2), 256, SMEM_FLASH>>>();
    combine2_kernel<<<S_N / 256, 256>>>();
    gate_kernel<<<(S_N * SRC / 4) / 256, 256>>>(x1, y);
}

// round 9
// speedup vs baseline: 7.1232x; 1.0735x over previous
#include <cuda_runtime.h>
#include <cuda_fp16.h>
#include <math_constants.h>

#define S_N   8192
#define SRC   768
#define DK    128
#define DV    64
#define KSPLIT 4
#define NIT   (S_N / KSPLIT / 64)   /* 32 key tiles per CTA */

typedef unsigned long long ull;
typedef unsigned int u32;

// ---------------- scratch (no allocations allowed) ----------------
__device__ __half g_Qf[S_N * DK];   // Q * log2e/sqrt(dk), fp16
__device__ __half g_Kf[S_N * DK];   // K, fp16
__device__ float g_vs[S_N];         // scalar V per key
__device__ float g_pl[KSPLIT * S_N], g_pa[KSPLIT * S_N];  // split partials
__device__ float g_out[S_N];        // gate scalar per query
__device__ float g_wvo[SRC];        // w_output @ w_v
__device__ float g_x2sum;

// ---------------- helpers ------------------------------------------
__device__ __forceinline__ float ex2f(float x) {
    float y; asm("ex2.approx.f32 %0, %1;" : "=f"(y) : "f"(x)); return y;
}
__device__ __forceinline__ u32 smem_u32(const void* p) {
    u32 a; asm("{ .reg .u64 t; cvta.to.shared.u64 t, %1; cvt.u32.u64 %0, t; }" : "=r"(a) : "l"(p));
    return a;
}
__device__ __forceinline__ void ldsm_x4(u32& r0, u32& r1, u32& r2, u32& r3, u32 addr) {
    asm volatile("ldmatrix.sync.aligned.m8n8.x4.shared.b16 {%0,%1,%2,%3}, [%4];"
                 : "=r"(r0), "=r"(r1), "=r"(r2), "=r"(r3) : "r"(addr));
}
__device__ __forceinline__ void mma16816(float& d0, float& d1, float& d2, float& d3,
                                         u32 a0, u32 a1, u32 a2, u32 a3,
                                         u32 b0, u32 b1) {
    asm volatile("mma.sync.aligned.m16n8k16.row.col.f32.f16.f16.f32 "
                 "{%0,%1,%2,%3},{%4,%5,%6,%7},{%8,%9},{%0,%1,%2,%3};"
                 : "+f"(d0), "+f"(d1), "+f"(d2), "+f"(d3)
                 : "r"(a0), "r"(a1), "r"(a2), "r"(a3), "r"(b0), "r"(b1));
}
__device__ __forceinline__ uint4 cvt8h(float4 a, float4 b) {
    __half2 h0 = __floats2half2_rn(a.x, a.y);
    __half2 h1 = __floats2half2_rn(a.z, a.w);
    __half2 h2 = __floats2half2_rn(b.x, b.y);
    __half2 h3 = __floats2half2_rn(b.z, b.w);
    uint4 u;
    u.x = *reinterpret_cast<u32*>(&h0);
    u.y = *reinterpret_cast<u32*>(&h1);
    u.z = *reinterpret_cast<u32*>(&h2);
    u.w = *reinterpret_cast<u32*>(&h3);
    return u;
}
__device__ __forceinline__ void cpa16(u32 dst, const void* src) {
    asm volatile("cp.async.cg.shared.global [%0], [%1], 16;" :: "r"(dst), "l"(src));
}
__device__ __forceinline__ void cpa4(u32 dst, const void* src) {
    asm volatile("cp.async.ca.shared.global [%0], [%1], 4;" :: "r"(dst), "l"(src));
}
__device__ __forceinline__ void cpa_commit() {
    asm volatile("cp.async.commit_group;" ::: "memory");
}
template <int N>
__device__ __forceinline__ void cpa_wait() {
    asm volatile("cp.async.wait_group %0;" :: "n"(N) : "memory");
}

// log2(e) / sqrt(128): folded into Q so softmax uses raw EX2, no max needed
#define CFOLD 0.12751743f

extern __shared__ char smem_raw[];

// ---------------- kernel 1: wvo = w_output @ w_v; zero flag --------
__global__ void prep_kernel(const float* __restrict__ w_v,
                            const float* __restrict__ w_out) {
    int c = threadIdx.x;
    if (c == 0) g_x2sum = 0.0f;
    if (c < SRC) {
        float acc = 0.0f;
        #pragma unroll
        for (int j = 0; j < DV; j++) acc += w_out[j] * w_v[j * SRC + c];
        g_wvo[c] = acc;
    }
}

// ---------------- kernel 2: Q/K projections on HMMA + fused vscalar --
// Y[8192,128] = X[8192,768] @ W[128,768]^T, fp16 out (Q pre-scaled).
// The K branch also computes v_s = x2 @ wvo and sum(x2) while staging x2.
#define PCH   12              /* 768 / 64 chunks */
#define SMEM_PROJ 65536       /* Xs[2][128][64]h + Ws[2][128][64]h */

__global__ void __launch_bounds__(512, 1)
proj_kernel(const float* __restrict__ x1, const float* __restrict__ x2,
            const float* __restrict__ wq, const float* __restrict__ wk) {
    const bool isQ = (blockIdx.y == 0);
    const float* X = isQ ? x1 : x2;
    const float* W = isQ ? wq : wk;
    __half* Y = isQ ? g_Qf : g_Kf;

    __shared__ float wvs[SRC];

    const int tid = threadIdx.x, lane = tid & 31, w = tid >> 5;
    const int qg = w & 3;         // 32-row group
    const int nh = w >> 2;        // 32-col group
    const int r0 = blockIdx.x * 128;

    if (!isQ) {
        if (tid < SRC) wvs[tid] = g_wvo[tid];
        if (tid >= SRC && tid < SRC + 256 && tid - SRC + 512 < SRC)
            wvs[tid - SRC + 512] = g_wvo[tid - SRC + 512];
        // simpler: cover 512..767 with threads 0..255 of second pass
    }
    if (!isQ && tid < 256) wvs[512 + tid] = g_wvo[512 + tid];
    __syncthreads();

    // staging map: 1024 uint4 slots per matrix per chunk (128 rows x 8 ch)
    int srow[2], sch[2];
    #pragma unroll
    for (int i = 0; i < 2; i++) {
        int idx = tid + i * 512;
        srow[i] = idx >> 3;
        sch[i]  = idx & 7;
    }

    float vsacc[2] = {0.0f, 0.0f};
    float xsum = 0.0f;

    uint4 pX[2], pW[2];
    auto load_regs = [&](int kk) {
        #pragma unroll
        for (int i = 0; i < 2; i++) {
            const float* sx = &X[(size_t)(r0 + srow[i]) * SRC + kk + sch[i] * 8];
            float4 a = *reinterpret_cast<const float4*>(sx);
            float4 b = *reinterpret_cast<const float4*>(sx + 4);
            if (!isQ) {
                const float* wv = &wvs[kk + sch[i] * 8];
                vsacc[i] = fmaf(a.x, wv[0], vsacc[i]);
                vsacc[i] = fmaf(a.y, wv[1], vsacc[i]);
                vsacc[i] = fmaf(a.z, wv[2], vsacc[i]);
                vsacc[i] = fmaf(a.w, wv[3], vsacc[i]);
                vsacc[i] = fmaf(b.x, wv[4], vsacc[i]);
                vsacc[i] = fmaf(b.y, wv[5], vsacc[i]);
                vsacc[i] = fmaf(b.z, wv[6], vsacc[i]);
                vsacc[i] = fmaf(b.w, wv[7], vsacc[i]);
                xsum += (a.x + a.y) + (a.z + a.w) + (b.x + b.y) + (b.z + b.w);
            }
            pX[i] = cvt8h(a, b);
            const float* sw = &W[(size_t)srow[i] * SRC + kk + sch[i] * 8];
            pW[i] = cvt8h(*reinterpret_cast<const float4*>(sw),
                          *reinterpret_cast<const float4*>(sw + 4));
        }
    };
    auto store_smem = [&](int buf) {
        char* xb = smem_raw + buf * 16384;
        char* wb = smem_raw + 32768 + buf * 16384;
        #pragma unroll
        for (int i = 0; i < 2; i++) {
            u32 dst = (u32)(srow[i] * 128) + (u32)((sch[i] ^ (srow[i] & 7)) << 4);
            *reinterpret_cast<uint4*>(xb + dst) = pX[i];
            *reinterpret_cast<uint4*>(wb + dst) = pW[i];
        }
    };

    float c[2][4][4];
    #pragma unroll
    for (int mt = 0; mt < 2; mt++)
        #pragma unroll
        for (int j = 0; j < 4; j++)
            #pragma unroll
            for (int e = 0; e < 4; e++) c[mt][j][e] = 0.0f;

    const u32 sX = smem_u32(smem_raw);
    const u32 sW = smem_u32(smem_raw) + 32768;
    const int rbA = qg * 32 + (lane & 7) + (lane & 8);
    const int kbitA = lane >> 4;
    const int rbB = nh * 32 + (lane & 7) + ((lane & 16) >> 1);
    const int kbitB = (lane >> 3) & 1;

    load_regs(0);
    for (int cidx = 0; cidx < PCH; cidx++) {
        const int buf = cidx & 1;
        store_smem(buf);
        __syncthreads();
        if (cidx + 1 < PCH) load_regs((cidx + 1) * 64);

        const u32 xb = sX + buf * 16384;
        const u32 wb = sW + buf * 16384;
        #pragma unroll
        for (int ks = 0; ks < 4; ks++) {
            u32 A0[4], A1[4];
            int chA = ks * 2 + kbitA;
            {
                int r = rbA;
                ldsm_x4(A0[0], A0[1], A0[2], A0[3], xb + r * 128 + ((chA ^ (r & 7)) << 4));
            }
            {
                int r = rbA + 16;
                ldsm_x4(A1[0], A1[1], A1[2], A1[3], xb + r * 128 + ((chA ^ (r & 7)) << 4));
            }
            int chB = ks * 2 + kbitB;
            #pragma unroll
            for (int nt = 0; nt < 2; nt++) {
                u32 b[4];
                int r = rbB + nt * 16;
                ldsm_x4(b[0], b[1], b[2], b[3], wb + r * 128 + ((chB ^ (r & 7)) << 4));
                mma16816(c[0][nt*2+0][0], c[0][nt*2+0][1], c[0][nt*2+0][2], c[0][nt*2+0][3],
                         A0[0], A0[1], A0[2], A0[3], b[0], b[1]);
                mma16816(c[0][nt*2+1][0], c[0][nt*2+1][1], c[0][nt*2+1][2], c[0][nt*2+1][3],
                         A0[0], A0[1], A0[2], A0[3], b[2], b[3]);
                mma16816(c[1][nt*2+0][0], c[1][nt*2+0][1], c[1][nt*2+0][2], c[1][nt*2+0][3],
                         A1[0], A1[1], A1[2], A1[3], b[0], b[1]);
                mma16816(c[1][nt*2+1][0], c[1][nt*2+1][1], c[1][nt*2+1][2], c[1][nt*2+1][3],
                         A1[0], A1[1], A1[2], A1[3], b[2], b[3]);
            }
        }
        __syncthreads();
    }

    // fused vscalar epilogue (K branch): reduce over 8-lane row groups
    if (!isQ) {
        #pragma unroll
        for (int m = 1; m < 8; m <<= 1) {
            vsacc[0] += __shfl_xor_sync(0xffffffffu, vsacc[0], m);
            vsacc[1] += __shfl_xor_sync(0xffffffffu, vsacc[1], m);
            xsum     += __shfl_xor_sync(0xffffffffu, xsum, m);
        }
        if ((lane & 7) == 0) {
            g_vs[r0 + srow[0]] = vsacc[0];
            g_vs[r0 + srow[1]] = vsacc[1];
            atomicAdd(&g_x2sum, xsum);
        }
    }

    const float scale = isQ ? CFOLD : 1.0f;
    #pragma unroll
    for (int mt = 0; mt < 2; mt++) {
        int row = r0 + qg * 32 + mt * 16 + (lane >> 2);
        #pragma unroll
        for (int j = 0; j < 4; j++) {
            int col = nh * 32 + j * 8 + (lane & 3) * 2;
            __half2 lo = __floats2half2_rn(c[mt][j][0] * scale, c[mt][j][1] * scale);
            __half2 hi = __floats2half2_rn(c[mt][j][2] * scale, c[mt][j][3] * scale);
            *reinterpret_cast<__half2*>(&Y[(size_t)row * DK + col]) = lo;
            *reinterpret_cast<__half2*>(&Y[(size_t)(row + 8) * DK + col]) = hi;
        }
    }
}

// ---------------- kernel 3: HMMA flash attention (scalar V) --------
// CTA: 128 queries x 64-key tiles, 8 warps (warp = 32q x 32k).
// grid (64, KSPLIT). cp.async 3-stage K ring, 1 barrier/iter.
#define OFF_KS   32768         /* __half Ks[3][64][128] */
#define OFF_VSB  81920         /* float vsb[3][64] */
#define OFF_RL   82688         /* float rl[2][128] */
#define OFF_RA   83712         /* float ra[2][128] */
#define SMEM_FLASH 84736

__global__ void __launch_bounds__(256, 2) flash_kernel() {
    float* vsb = reinterpret_cast<float*>(smem_raw + OFF_VSB);
    float* rl  = reinterpret_cast<float*>(smem_raw + OFF_RL);
    float* ra  = reinterpret_cast<float*>(smem_raw + OFF_RA);

    const int tid = threadIdx.x, lane = tid & 31, w = tid >> 5;
    const int q0 = blockIdx.x * 128;
    const int k0 = blockIdx.y * (S_N / KSPLIT);
    const int kh = w >> 2;       // key half within tile (0/1)
    const int qg = w & 3;        // 32-query group
    const u32 sbase = smem_u32(smem_raw);

    // per-thread K staging slot
    const int krow = tid >> 4, kch = tid & 15;     // +64 rows per i
    const u32 kdst0 = (u32)(krow * 256) + (u32)((kch ^ (krow & 7)) << 4);

    auto issue_tile = [&](int it) {
        const int slot = it % 3;
        const int t0 = k0 + it * 64;
        #pragma unroll
        for (int i = 0; i < 4; i++) {
            int row = krow + i * 16;
            u32 dst = sbase + OFF_KS + slot * 16384 +
                      (u32)(row * 256) + (u32)((kch ^ (row & 7)) << 4);
            cpa16(dst, g_Kf + (size_t)(t0 + row) * DK + kch * 8);
        }
        if (tid < 64)
            cpa4(sbase + OFF_VSB + slot * 256 + tid * 4, &g_vs[t0 + tid]);
        cpa_commit();
    };

    issue_tile(0);
    issue_tile(1);

    // stage Q (XOR-swizzled)
    #pragma unroll
    for (int i = 0; i < 8; i++) {
        int idx = tid + i * 256;
        int row = idx >> 4, ch = idx & 15;
        u32 dst = (u32)(row * 256) + (u32)((ch ^ (row & 7)) << 4);
        *reinterpret_cast<uint4*>(smem_raw + dst) =
            *reinterpret_cast<const uint4*>(g_Qf + (size_t)(q0 + row) * DK + ch * 8);
    }
    __syncthreads();

    // A fragments: register-resident for the whole CTA lifetime
    u32 A[2][8][4];
    {
        int rb = qg * 32 + (lane & 7) + (lane & 8);
        int kbit = lane >> 4;
        #pragma unroll
        for (int mt = 0; mt < 2; mt++) {
            int row = rb + mt * 16;
            #pragma unroll
            for (int ks = 0; ks < 8; ks++) {
                int ch = ks * 2 + kbit;
                ldsm_x4(A[mt][ks][0], A[mt][ks][1], A[mt][ks][2], A[mt][ks][3],
                        sbase + row * 256 + ((ch ^ (row & 7)) << 4));
            }
        }
    }

    const u32 sK = sbase + OFF_KS;
    const int rB0 = kh * 32 + (lane & 7) + ((lane & 16) >> 1);
    const int kbitB = (lane >> 3) & 1;

    float l_[4] = {0, 0, 0, 0}, a_[4] = {0, 0, 0, 0};

    for (int it = 0; it < NIT; it++) {
        const int slot = it % 3;
        if (it + 1 < NIT) cpa_wait<1>(); else cpa_wait<0>();
        __syncthreads();
        if (it + 2 < NIT) issue_tile(it + 2);

        // ---- QK^T on tensor cores ----
        float c[2][4][4];
        #pragma unroll
        for (int mt = 0; mt < 2; mt++)
            #pragma unroll
            for (int j = 0; j < 4; j++)
                #pragma unroll
                for (int e = 0; e < 4; e++) c[mt][j][e] = 0.0f;

        const u32 kb = sK + slot * 16384;
        #pragma unroll
        for (int ks = 0; ks < 8; ks++) {
            u32 b[8];
            int ch = ks * 2 + kbitB;
            {
                int row = rB0;
                ldsm_x4(b[0], b[1], b[2], b[3],
                        kb + row * 256 + ((ch ^ (row & 7)) << 4));
            }
            {
                int row = rB0 + 16;
                ldsm_x4(b[4], b[5], b[6], b[7],
                        kb + row * 256 + ((ch ^ (row & 7)) << 4));
            }
            #pragma unroll
            for (int mt = 0; mt < 2; mt++) {
                mma16816(c[mt][0][0], c[mt][0][1], c[mt][0][2], c[mt][0][3],
                         A[mt][ks][0], A[mt][ks][1], A[mt][ks][2], A[mt][ks][3], b[0], b[1]);
                mma16816(c[mt][1][0], c[mt][1][1], c[mt][1][2], c[mt][1][3],
                         A[mt][ks][0], A[mt][ks][1], A[mt][ks][2], A[mt][ks][3], b[2], b[3]);
                mma16816(c[mt][2][0], c[mt][2][1], c[mt][2][2], c[mt][2][3],
                         A[mt][ks][0], A[mt][ks][1], A[mt][ks][2], A[mt][ks][3], b[4], b[5]);
                mma16816(c[mt][3][0], c[mt][3][1], c[mt][3][2], c[mt][3][3],
                         A[mt][ks][0], A[mt][ks][1], A[mt][ks][2], A[mt][ks][3], b[6], b[7]);
            }
        }

        // ---- softmax accumulate (no max: p = 2^s, scores are small) ----
        const float* vv = vsb + slot * 64 + kh * 32 + (lane & 3) * 2;
        #pragma unroll
        for (int j = 0; j < 4; j++) {
            float2 vs2 = *reinterpret_cast<const float2*>(vv + j * 8);
            #pragma unroll
            for (int mt = 0; mt < 2; mt++) {
                float p0 = ex2f(c[mt][j][0]);
                float p1 = ex2f(c[mt][j][1]);
                float p2 = ex2f(c[mt][j][2]);
                float p3 = ex2f(c[mt][j][3]);
                l_[mt * 2 + 0] += p0 + p1;
                l_[mt * 2 + 1] += p2 + p3;
                a_[mt * 2 + 0] = fmaf(p0, vs2.x, fmaf(p1, vs2.y, a_[mt * 2 + 0]));
                a_[mt * 2 + 1] = fmaf(p2, vs2.x, fmaf(p3, vs2.y, a_[mt * 2 + 1]));
            }
        }
    }

    // quad reduce (lanes sharing a row are lane^1, lane^2)
    #pragma unroll
    for (int r = 0; r < 4; r++) {
        l_[r] += __shfl_xor_sync(0xffffffffu, l_[r], 1);
        l_[r] += __shfl_xor_sync(0xffffffffu, l_[r], 2);
        a_[r] += __shfl_xor_sync(0xffffffffu, a_[r], 1);
        a_[r] += __shfl_xor_sync(0xffffffffu, a_[r], 2);
    }
    __syncthreads();
    if ((lane & 3) == 0) {
        int gid = lane >> 2;
        #pragma unroll
        for (int r = 0; r < 4; r++) {
            int mt = r >> 1, hi = r & 1;
            int qrow = qg * 32 + mt * 16 + gid + hi * 8;
            rl[kh * 128 + qrow] = l_[r];
            ra[kh * 128 + qrow] = a_[r];
        }
    }
    __syncthreads();
    if (tid < 128) {
        int r = blockIdx.y * S_N + q0 + tid;
        g_pl[r] = rl[tid] + rl[128 + tid];
        g_pa[r] = ra[tid] + ra[128 + tid];
    }
}

// ---------------- kernel 4: combine key-splits ---------------------
__global__ void combine_kernel() {
    int r = blockIdx.x * 256 + threadIdx.x;
    float L = 0.0f, A = 0.0f;
    #pragma unroll
    for (int s = 0; s < KSPLIT; s++) {
        L += g_pl[s * S_N + r];
        A += g_pa[s * S_N + r];
    }
    g_out[r] = A / L;
}

// ---------------- kernel 5: y = x1 * (1 - out) (or x1 if sum==0) ---
__global__ void gate_kernel(const float* __restrict__ x1, float* __restrict__ y) {
    int i = blockIdx.x * 256 + threadIdx.x;
    float4 v = reinterpret_cast<const float4*>(x1)[i];
    int row = i / (SRC / 4);
    float g = (g_x2sum == 0.0f) ? 0.0f : g_out[row];
    float f = 1.0f - g;
    v.x *= f; v.y *= f; v.z *= f; v.w *= f;
    reinterpret_cast<float4*>(y)[i] = v;
}

// ---------------- launch ------------------------------------------
extern "C" void kernel_launch(void* const* d_in, const int* in_sizes, int n_in,
                              void* d_out, int out_size) {
    const float* x1 = (const float*)d_in[0];
    const float* x2 = (const float*)d_in[1];
    const float* wq = (const float*)d_in[2];
    const float* wk = (const float*)d_in[3];
    const float* wv = (const float*)d_in[4];
    const float* wo = (const float*)d_in[5];
    float* y = (float*)d_out;

    cudaFuncSetAttribute(flash_kernel, cudaFuncAttributeMaxDynamicSharedMemorySize,
                         SMEM_FLASH);
    cudaFuncSetAttribute(proj_kernel, cudaFuncAttributeMaxDynamicSharedMemorySize,
                         SMEM_PROJ);

    prep_kernel<<<1, 768>>>(wv, wo);
    proj_kernel<<<dim3(S_N / 128, 2), 512, SMEM_PROJ>>>(x1, x2, wq, wk);
    flash_kernel<<<dim3(S_N / 128, KSPLIT), 256, SMEM_FLASH>>>();
    combine_kernel<<<S_N / 256, 256>>>();
    gate_kernel<<<(S_N * SRC / 4) / 256, 256>>>(x1, y);
}

// round 10
// speedup vs baseline: 7.7083x; 1.0822x over previous
#include <cuda_runtime.h>
#include <cuda_fp16.h>
#include <math_constants.h>

#define S_N   8192
#define SRC   768
#define DK    128
#define DV    64
#define KSPLIT 4
#define NIT   (S_N / KSPLIT / 64)   /* 32 key tiles per CTA */

typedef unsigned long long ull;
typedef unsigned int u32;

// ---------------- scratch (no allocations allowed) ----------------
__device__ __half g_Qf[S_N * DK];   // Q * log2e/sqrt(dk), fp16
__device__ __half g_Kf[S_N * DK];   // K, fp16
__device__ float g_vs[S_N];         // scalar V per key
__device__ float g_pl[KSPLIT * S_N], g_pa[KSPLIT * S_N];  // split partials
__device__ float g_wvo[SRC];        // w_output @ w_v
__device__ float g_x2sum;

// ---------------- helpers ------------------------------------------
__device__ __forceinline__ u32 smem_u32(const void* p) {
    u32 a; asm("{ .reg .u64 t; cvta.to.shared.u64 t, %1; cvt.u32.u64 %0, t; }" : "=r"(a) : "l"(p));
    return a;
}
__device__ __forceinline__ void ldsm_x4(u32& r0, u32& r1, u32& r2, u32& r3, u32 addr) {
    asm volatile("ldmatrix.sync.aligned.m8n8.x4.shared.b16 {%0,%1,%2,%3}, [%4];"
                 : "=r"(r0), "=r"(r1), "=r"(r2), "=r"(r3) : "r"(addr));
}
// f32-accumulator HMMA (projection kernel)
__device__ __forceinline__ void mma16816(float& d0, float& d1, float& d2, float& d3,
                                         u32 a0, u32 a1, u32 a2, u32 a3,
                                         u32 b0, u32 b1) {
    asm volatile("mma.sync.aligned.m16n8k16.row.col.f32.f16.f16.f32 "
                 "{%0,%1,%2,%3},{%4,%5,%6,%7},{%8,%9},{%0,%1,%2,%3};"
                 : "+f"(d0), "+f"(d1), "+f"(d2), "+f"(d3)
                 : "r"(a0), "r"(a1), "r"(a2), "r"(a3), "r"(b0), "r"(b1));
}
// f16-accumulator HMMA (flash kernel: 2x tensor rate, half the C regs)
__device__ __forceinline__ void mma16816h(u32& d0, u32& d1,
                                          u32 a0, u32 a1, u32 a2, u32 a3,
                                          u32 b0, u32 b1) {
    asm volatile("mma.sync.aligned.m16n8k16.row.col.f16.f16.f16.f16 "
                 "{%0,%1},{%2,%3,%4,%5},{%6,%7},{%0,%1};"
                 : "+r"(d0), "+r"(d1)
                 : "r"(a0), "r"(a1), "r"(a2), "r"(a3), "r"(b0), "r"(b1));
}
__device__ __forceinline__ u32 ex2h2(u32 x) {
    u32 y; asm("ex2.approx.f16x2 %0, %1;" : "=r"(y) : "r"(x)); return y;
}
__device__ __forceinline__ u32 hadd2u(u32 a, u32 b) {
    u32 d; asm("add.f16x2 %0, %1, %2;" : "=r"(d) : "r"(a), "r"(b)); return d;
}
__device__ __forceinline__ uint4 cvt8h(float4 a, float4 b) {
    __half2 h0 = __floats2half2_rn(a.x, a.y);
    __half2 h1 = __floats2half2_rn(a.z, a.w);
    __half2 h2 = __floats2half2_rn(b.x, b.y);
    __half2 h3 = __floats2half2_rn(b.z, b.w);
    uint4 u;
    u.x = *reinterpret_cast<u32*>(&h0);
    u.y = *reinterpret_cast<u32*>(&h1);
    u.z = *reinterpret_cast<u32*>(&h2);
    u.w = *reinterpret_cast<u32*>(&h3);
    return u;
}
__device__ __forceinline__ void cpa16(u32 dst, const void* src) {
    asm volatile("cp.async.cg.shared.global [%0], [%1], 16;" :: "r"(dst), "l"(src));
}
__device__ __forceinline__ void cpa4(u32 dst, const void* src) {
    asm volatile("cp.async.ca.shared.global [%0], [%1], 4;" :: "r"(dst), "l"(src));
}
__device__ __forceinline__ void cpa_commit() {
    asm volatile("cp.async.commit_group;" ::: "memory");
}
template <int N>
__device__ __forceinline__ void cpa_wait() {
    asm volatile("cp.async.wait_group %0;" :: "n"(N) : "memory");
}

// log2(e) / sqrt(128): folded into Q so softmax uses raw EX2, no max needed
#define CFOLD 0.12751743f

extern __shared__ char smem_raw[];

// ---------------- kernel 1: wvo = w_output @ w_v; zero flag --------
__global__ void prep_kernel(const float* __restrict__ w_v,
                            const float* __restrict__ w_out) {
    int c = threadIdx.x;
    if (c == 0) g_x2sum = 0.0f;
    if (c < SRC) {
        float acc = 0.0f;
        #pragma unroll
        for (int j = 0; j < DV; j++) acc += w_out[j] * w_v[j * SRC + c];
        g_wvo[c] = acc;
    }
}

// ---------------- kernel 2: Q/K projections on HMMA + fused vscalar --
#define PCH   12              /* 768 / 64 chunks */
#define SMEM_PROJ 65536       /* Xs[2][128][64]h + Ws[2][128][64]h */

__global__ void __launch_bounds__(512, 1)
proj_kernel(const float* __restrict__ x1, const float* __restrict__ x2,
            const float* __restrict__ wq, const float* __restrict__ wk) {
    const bool isQ = (blockIdx.y == 0);
    const float* X = isQ ? x1 : x2;
    const float* W = isQ ? wq : wk;
    __half* Y = isQ ? g_Qf : g_Kf;

    __shared__ float wvs[SRC];

    const int tid = threadIdx.x, lane = tid & 31, w = tid >> 5;
    const int qg = w & 3;         // 32-row group
    const int nh = w >> 2;        // 32-col group
    const int r0 = blockIdx.x * 128;

    if (!isQ) {
        if (tid < SRC) wvs[tid] = g_wvo[tid];
        if (tid < 256) wvs[512 + tid] = g_wvo[512 + tid];
    }
    __syncthreads();

    int srow[2], sch[2];
    #pragma unroll
    for (int i = 0; i < 2; i++) {
        int idx = tid + i * 512;
        srow[i] = idx >> 3;
        sch[i]  = idx & 7;
    }

    float vsacc[2] = {0.0f, 0.0f};
    float xsum = 0.0f;

    uint4 pX[2], pW[2];
    auto load_regs = [&](int kk) {
        #pragma unroll
        for (int i = 0; i < 2; i++) {
            const float* sx = &X[(size_t)(r0 + srow[i]) * SRC + kk + sch[i] * 8];
            float4 a = *reinterpret_cast<const float4*>(sx);
            float4 b = *reinterpret_cast<const float4*>(sx + 4);
            if (!isQ) {
                const float* wv = &wvs[kk + sch[i] * 8];
                vsacc[i] = fmaf(a.x, wv[0], vsacc[i]);
                vsacc[i] = fmaf(a.y, wv[1], vsacc[i]);
                vsacc[i] = fmaf(a.z, wv[2], vsacc[i]);
                vsacc[i] = fmaf(a.w, wv[3], vsacc[i]);
                vsacc[i] = fmaf(b.x, wv[4], vsacc[i]);
                vsacc[i] = fmaf(b.y, wv[5], vsacc[i]);
                vsacc[i] = fmaf(b.z, wv[6], vsacc[i]);
                vsacc[i] = fmaf(b.w, wv[7], vsacc[i]);
                xsum += (a.x + a.y) + (a.z + a.w) + (b.x + b.y) + (b.z + b.w);
            }
            pX[i] = cvt8h(a, b);
            const float* sw = &W[(size_t)srow[i] * SRC + kk + sch[i] * 8];
            pW[i] = cvt8h(*reinterpret_cast<const float4*>(sw),
                          *reinterpret_cast<const float4*>(sw + 4));
        }
    };
    auto store_smem = [&](int buf) {
        char* xb = smem_raw + buf * 16384;
        char* wb = smem_raw + 32768 + buf * 16384;
        #pragma unroll
        for (int i = 0; i < 2; i++) {
            u32 dst = (u32)(srow[i] * 128) + (u32)((sch[i] ^ (srow[i] & 7)) << 4);
            *reinterpret_cast<uint4*>(xb + dst) = pX[i];
            *reinterpret_cast<uint4*>(wb + dst) = pW[i];
        }
    };

    float c[2][4][4];
    #pragma unroll
    for (int mt = 0; mt < 2; mt++)
        #pragma unroll
        for (int j = 0; j < 4; j++)
            #pragma unroll
            for (int e = 0; e < 4; e++) c[mt][j][e] = 0.0f;

    const u32 sX = smem_u32(smem_raw);
    const u32 sW = smem_u32(smem_raw) + 32768;
    const int rbA = qg * 32 + (lane & 7) + (lane & 8);
    const int kbitA = lane >> 4;
    const int rbB = nh * 32 + (lane & 7) + ((lane & 16) >> 1);
    const int kbitB = (lane >> 3) & 1;

    load_regs(0);
    for (int cidx = 0; cidx < PCH; cidx++) {
        const int buf = cidx & 1;
        store_smem(buf);
        __syncthreads();
        if (cidx + 1 < PCH) load_regs((cidx + 1) * 64);

        const u32 xb = sX + buf * 16384;
        const u32 wb = sW + buf * 16384;
        #pragma unroll
        for (int ks = 0; ks < 4; ks++) {
            u32 A0[4], A1[4];
            int chA = ks * 2 + kbitA;
            {
                int r = rbA;
                ldsm_x4(A0[0], A0[1], A0[2], A0[3], xb + r * 128 + ((chA ^ (r & 7)) << 4));
            }
            {
                int r = rbA + 16;
                ldsm_x4(A1[0], A1[1], A1[2], A1[3], xb + r * 128 + ((chA ^ (r & 7)) << 4));
            }
            int chB = ks * 2 + kbitB;
            #pragma unroll
            for (int nt = 0; nt < 2; nt++) {
                u32 b[4];
                int r = rbB + nt * 16;
                ldsm_x4(b[0], b[1], b[2], b[3], wb + r * 128 + ((chB ^ (r & 7)) << 4));
                mma16816(c[0][nt*2+0][0], c[0][nt*2+0][1], c[0][nt*2+0][2], c[0][nt*2+0][3],
                         A0[0], A0[1], A0[2], A0[3], b[0], b[1]);
                mma16816(c[0][nt*2+1][0], c[0][nt*2+1][1], c[0][nt*2+1][2], c[0][nt*2+1][3],
                         A0[0], A0[1], A0[2], A0[3], b[2], b[3]);
                mma16816(c[1][nt*2+0][0], c[1][nt*2+0][1], c[1][nt*2+0][2], c[1][nt*2+0][3],
                         A1[0], A1[1], A1[2], A1[3], b[0], b[1]);
                mma16816(c[1][nt*2+1][0], c[1][nt*2+1][1], c[1][nt*2+1][2], c[1][nt*2+1][3],
                         A1[0], A1[1], A1[2], A1[3], b[2], b[3]);
            }
        }
        __syncthreads();
    }

    if (!isQ) {
        #pragma unroll
        for (int m = 1; m < 8; m <<= 1) {
            vsacc[0] += __shfl_xor_sync(0xffffffffu, vsacc[0], m);
            vsacc[1] += __shfl_xor_sync(0xffffffffu, vsacc[1], m);
            xsum     += __shfl_xor_sync(0xffffffffu, xsum, m);
        }
        if ((lane & 7) == 0) {
            g_vs[r0 + srow[0]] = vsacc[0];
            g_vs[r0 + srow[1]] = vsacc[1];
            atomicAdd(&g_x2sum, xsum);
        }
    }

    const float scale = isQ ? CFOLD : 1.0f;
    #pragma unroll
    for (int mt = 0; mt < 2; mt++) {
        int row = r0 + qg * 32 + mt * 16 + (lane >> 2);
        #pragma unroll
        for (int j = 0; j < 4; j++) {
            int col = nh * 32 + j * 8 + (lane & 3) * 2;
            __half2 lo = __floats2half2_rn(c[mt][j][0] * scale, c[mt][j][1] * scale);
            __half2 hi = __floats2half2_rn(c[mt][j][2] * scale, c[mt][j][3] * scale);
            *reinterpret_cast<__half2*>(&Y[(size_t)row * DK + col]) = lo;
            *reinterpret_cast<__half2*>(&Y[(size_t)(row + 8) * DK + col]) = hi;
        }
    }
}

// ---------------- kernel 3: HMMA flash attention, f16 accumulators --
// CTA: 128 queries x 64-key tiles, 8 warps (warp = 32q x 32k).
// grid (64, KSPLIT). cp.async 3-stage K ring, 1 barrier/iter.
// Scores accumulate in fp16 (2x tensor rate), exp via ex2.f16x2 (2x MUFU),
// l in half2 with per-iter fp32 flush, a in fp32.
#define OFF_KS   32768         /* __half Ks[3][64][128] */
#define OFF_VSB  81920         /* float vsb[3][64] */
#define OFF_RL   82688         /* float rl[2][128] */
#define OFF_RA   83712         /* float ra[2][128] */
#define SMEM_FLASH 84736

__global__ void __launch_bounds__(256, 2) flash_kernel() {
    float* vsb = reinterpret_cast<float*>(smem_raw + OFF_VSB);
    float* rl  = reinterpret_cast<float*>(smem_raw + OFF_RL);
    float* ra  = reinterpret_cast<float*>(smem_raw + OFF_RA);

    const int tid = threadIdx.x, lane = tid & 31, w = tid >> 5;
    const int q0 = blockIdx.x * 128;
    const int k0 = blockIdx.y * (S_N / KSPLIT);
    const int kh = w >> 2;       // key half within tile (0/1)
    const int qg = w & 3;        // 32-query group
    const u32 sbase = smem_u32(smem_raw);

    const int krow = tid >> 4, kch = tid & 15;

    auto issue_tile = [&](int it) {
        const int slot = it % 3;
        const int t0 = k0 + it * 64;
        #pragma unroll
        for (int i = 0; i < 4; i++) {
            int row = krow + i * 16;
            u32 dst = sbase + OFF_KS + slot * 16384 +
                      (u32)(row * 256) + (u32)((kch ^ (row & 7)) << 4);
            cpa16(dst, g_Kf + (size_t)(t0 + row) * DK + kch * 8);
        }
        if (tid < 64)
            cpa4(sbase + OFF_VSB + slot * 256 + tid * 4, &g_vs[t0 + tid]);
        cpa_commit();
    };

    issue_tile(0);
    issue_tile(1);

    // stage Q (XOR-swizzled)
    #pragma unroll
    for (int i = 0; i < 8; i++) {
        int idx = tid + i * 256;
        int row = idx >> 4, ch = idx & 15;
        u32 dst = (u32)(row * 256) + (u32)((ch ^ (row & 7)) << 4);
        *reinterpret_cast<uint4*>(smem_raw + dst) =
            *reinterpret_cast<const uint4*>(g_Qf + (size_t)(q0 + row) * DK + ch * 8);
    }
    __syncthreads();

    // A fragments: register-resident for the whole CTA lifetime
    u32 A[2][8][4];
    {
        int rb = qg * 32 + (lane & 7) + (lane & 8);
        int kbit = lane >> 4;
        #pragma unroll
        for (int mt = 0; mt < 2; mt++) {
            int row = rb + mt * 16;
            #pragma unroll
            for (int ks = 0; ks < 8; ks++) {
                int ch = ks * 2 + kbit;
                ldsm_x4(A[mt][ks][0], A[mt][ks][1], A[mt][ks][2], A[mt][ks][3],
                        sbase + row * 256 + ((ch ^ (row & 7)) << 4));
            }
        }
    }

    const u32 sK = sbase + OFF_KS;
    const int rB0 = kh * 32 + (lane & 7) + ((lane & 16) >> 1);
    const int kbitB = (lane >> 3) & 1;

    float l_[4] = {0, 0, 0, 0}, a_[4] = {0, 0, 0, 0};

    for (int it = 0; it < NIT; it++) {
        const int slot = it % 3;
        if (it + 1 < NIT) cpa_wait<1>(); else cpa_wait<0>();
        __syncthreads();
        if (it + 2 < NIT) issue_tile(it + 2);

        // ---- QK^T on tensor cores, fp16 accumulators ----
        u32 c2[2][4][2];
        #pragma unroll
        for (int mt = 0; mt < 2; mt++)
            #pragma unroll
            for (int j = 0; j < 4; j++) {
                c2[mt][j][0] = 0u;
                c2[mt][j][1] = 0u;
            }

        const u32 kb = sK + slot * 16384;
        #pragma unroll
        for (int ks = 0; ks < 8; ks++) {
            u32 b[8];
            int ch = ks * 2 + kbitB;
            {
                int row = rB0;
                ldsm_x4(b[0], b[1], b[2], b[3],
                        kb + row * 256 + ((ch ^ (row & 7)) << 4));
            }
            {
                int row = rB0 + 16;
                ldsm_x4(b[4], b[5], b[6], b[7],
                        kb + row * 256 + ((ch ^ (row & 7)) << 4));
            }
            #pragma unroll
            for (int mt = 0; mt < 2; mt++) {
                mma16816h(c2[mt][0][0], c2[mt][0][1],
                          A[mt][ks][0], A[mt][ks][1], A[mt][ks][2], A[mt][ks][3], b[0], b[1]);
                mma16816h(c2[mt][1][0], c2[mt][1][1],
                          A[mt][ks][0], A[mt][ks][1], A[mt][ks][2], A[mt][ks][3], b[2], b[3]);
                mma16816h(c2[mt][2][0], c2[mt][2][1],
                          A[mt][ks][0], A[mt][ks][1], A[mt][ks][2], A[mt][ks][3], b[4], b[5]);
                mma16816h(c2[mt][3][0], c2[mt][3][1],
                          A[mt][ks][0], A[mt][ks][1], A[mt][ks][2], A[mt][ks][3], b[6], b[7]);
            }
        }

        // ---- softmax accumulate: p = 2^s via f16x2 MUFU ----
        // c2[mt][j][rr]: rows (qg*32 + mt*16 + lane/4 + rr*8), cols pair
        // (kh*32 + j*8 + (lane&3)*2) -- matches float2 loads from vsb.
        const float* vv = vsb + slot * 64 + kh * 32 + (lane & 3) * 2;
        u32 lh2[4] = {0u, 0u, 0u, 0u};
        #pragma unroll
        for (int j = 0; j < 4; j++) {
            float2 vs2 = *reinterpret_cast<const float2*>(vv + j * 8);
            #pragma unroll
            for (int mt = 0; mt < 2; mt++) {
                #pragma unroll
                for (int rr = 0; rr < 2; rr++) {
                    u32 p2 = ex2h2(c2[mt][j][rr]);
                    __half2 ph = *reinterpret_cast<__half2*>(&p2);
                    float p0 = __low2float(ph);
                    float p1 = __high2float(ph);
                    a_[mt * 2 + rr] = fmaf(p0, vs2.x, fmaf(p1, vs2.y, a_[mt * 2 + rr]));
                    lh2[mt * 2 + rr] = hadd2u(lh2[mt * 2 + rr], p2);
                }
            }
        }
        #pragma unroll
        for (int r = 0; r < 4; r++) {
            __half2 lh = *reinterpret_cast<__half2*>(&lh2[r]);
            l_[r] += __low2float(lh) + __high2float(lh);
        }
    }

    // quad reduce (lanes sharing a row are lane^1, lane^2)
    #pragma unroll
    for (int r = 0; r < 4; r++) {
        l_[r] += __shfl_xor_sync(0xffffffffu, l_[r], 1);
        l_[r] += __shfl_xor_sync(0xffffffffu, l_[r], 2);
        a_[r] += __shfl_xor_sync(0xffffffffu, a_[r], 1);
        a_[r] += __shfl_xor_sync(0xffffffffu, a_[r], 2);
    }
    __syncthreads();
    if ((lane & 3) == 0) {
        int gid = lane >> 2;
        #pragma unroll
        for (int r = 0; r < 4; r++) {
            int mt = r >> 1, rr = r & 1;
            int qrow = qg * 32 + mt * 16 + gid + rr * 8;
            rl[kh * 128 + qrow] = l_[r];
            ra[kh * 128 + qrow] = a_[r];
        }
    }
    __syncthreads();
    if (tid < 128) {
        int r = blockIdx.y * S_N + q0 + tid;
        g_pl[r] = rl[tid] + rl[128 + tid];
        g_pa[r] = ra[tid] + ra[128 + tid];
    }
}

// ---------------- kernel 4: fused combine + gate -------------------
// y = x1 * (1 - out[row]) where out[row] = sum_s pa / sum_s pl.
// Each block covers 256 float4 = 1024 floats = spans <= 3 rows; the
// first 3 threads compute those rows' gates into smem.
__global__ void gate_kernel(const float* __restrict__ x1, float* __restrict__ y) {
    __shared__ float gs[3];
    const int b = blockIdx.x, tid = threadIdx.x;
    const int rlo = (b * 256) / 192;          // 192 float4 per row
    if (tid < 3) {
        int r = rlo + tid;
        float g = 0.0f;
        if (r < S_N && g_x2sum != 0.0f) {
            float L = 0.0f, A = 0.0f;
            #pragma unroll
            for (int s = 0; s < KSPLIT; s++) {
                L += g_pl[s * S_N + r];
                A += g_pa[s * S_N + r];
            }
            g = A / L;
        }
        gs[tid] = g;
    }
    __syncthreads();
    int i = b * 256 + tid;
    float4 v = reinterpret_cast<const float4*>(x1)[i];
    float f = 1.0f - gs[i / 192 - rlo];
    v.x *= f; v.y *= f; v.z *= f; v.w *= f;
    reinterpret_cast<float4*>(y)[i] = v;
}

// ---------------- launch ------------------------------------------
extern "C" void kernel_launch(void* const* d_in, const int* in_sizes, int n_in,
                              void* d_out, int out_size) {
    const float* x1 = (const float*)d_in[0];
    const float* x2 = (const float*)d_in[1];
    const float* wq = (const float*)d_in[2];
    const float* wk = (const float*)d_in[3];
    const float* wv = (const float*)d_in[4];
    const float* wo = (const float*)d_in[5];
    float* y = (float*)d_out;

    cudaFuncSetAttribute(flash_kernel, cudaFuncAttributeMaxDynamicSharedMemorySize,
                         SMEM_FLASH);
    cudaFuncSetAttribute(proj_kernel, cudaFuncAttributeMaxDynamicSharedMemorySize,
                         SMEM_PROJ);

    prep_kernel<<<1, 768>>>(wv, wo);
    proj_kernel<<<dim3(S_N / 128, 2), 512, SMEM_PROJ>>>(x1, x2, wq, wk);
    flash_kernel<<<dim3(S_N / 128, KSPLIT), 256, SMEM_FLASH>>>();
    gate_kernel<<<(S_N * SRC / 4) / 256, 256>>>(x1, y);
}

// round 12
// speedup vs baseline: 8.2297x; 1.0676x over previous
#include <cuda_runtime.h>
#include <cuda_fp16.h>
#include <math_constants.h>

#define S_N   8192
#define SRC   768
#define DK    128
#define DV    64
#define KSPLIT 4
#define NIT   (S_N / KSPLIT / 64)   /* 32 key tiles per CTA */

typedef unsigned long long ull;
typedef unsigned int u32;

// ---------------- scratch (no allocations allowed) ----------------
__device__ __half g_Qf[S_N * DK];   // Q * log2e/sqrt(dk), fp16
__device__ __half g_Kf[S_N * DK];   // K, fp16
__device__ float g_vs[S_N];         // scalar V per key
__device__ float g_pl[KSPLIT * S_N], g_pa[KSPLIT * S_N];  // split partials
__device__ float g_wvo[SRC];        // w_output @ w_v
__device__ float g_x2sum;

// ---------------- helpers ------------------------------------------
__device__ __forceinline__ u32 smem_u32(const void* p) {
    u32 a; asm("{ .reg .u64 t; cvta.to.shared.u64 t, %1; cvt.u32.u64 %0, t; }" : "=r"(a) : "l"(p));
    return a;
}
__device__ __forceinline__ void ldsm_x4(u32& r0, u32& r1, u32& r2, u32& r3, u32 addr) {
    asm volatile("ldmatrix.sync.aligned.m8n8.x4.shared.b16 {%0,%1,%2,%3}, [%4];"
                 : "=r"(r0), "=r"(r1), "=r"(r2), "=r"(r3) : "r"(addr));
}
// f32-accumulator HMMA (projection kernel)
__device__ __forceinline__ void mma16816(float& d0, float& d1, float& d2, float& d3,
                                         u32 a0, u32 a1, u32 a2, u32 a3,
                                         u32 b0, u32 b1) {
    asm volatile("mma.sync.aligned.m16n8k16.row.col.f32.f16.f16.f32 "
                 "{%0,%1,%2,%3},{%4,%5,%6,%7},{%8,%9},{%0,%1,%2,%3};"
                 : "+f"(d0), "+f"(d1), "+f"(d2), "+f"(d3)
                 : "r"(a0), "r"(a1), "r"(a2), "r"(a3), "r"(b0), "r"(b1));
}
// f16-accumulator HMMA (flash kernel: 2x tensor rate, half the C regs)
__device__ __forceinline__ void mma16816h(u32& d0, u32& d1,
                                          u32 a0, u32 a1, u32 a2, u32 a3,
                                          u32 b0, u32 b1) {
    asm volatile("mma.sync.aligned.m16n8k16.row.col.f16.f16.f16.f16 "
                 "{%0,%1},{%2,%3,%4,%5},{%6,%7},{%0,%1};"
                 : "+r"(d0), "+r"(d1)
                 : "r"(a0), "r"(a1), "r"(a2), "r"(a3), "r"(b0), "r"(b1));
}
__device__ __forceinline__ u32 ex2h2(u32 x) {
    u32 y; asm("ex2.approx.f16x2 %0, %1;" : "=r"(y) : "r"(x)); return y;
}
__device__ __forceinline__ u32 hadd2u(u32 a, u32 b) {
    u32 d; asm("add.f16x2 %0, %1, %2;" : "=r"(d) : "r"(a), "r"(b)); return d;
}
__device__ __forceinline__ u32 hfma2u(u32 a, u32 b, u32 c) {
    u32 d; asm("fma.rn.f16x2 %0, %1, %2, %3;" : "=r"(d) : "r"(a), "r"(b), "r"(c)); return d;
}
__device__ __forceinline__ uint4 cvt8h(float4 a, float4 b) {
    __half2 h0 = __floats2half2_rn(a.x, a.y);
    __half2 h1 = __floats2half2_rn(a.z, a.w);
    __half2 h2 = __floats2half2_rn(b.x, b.y);
    __half2 h3 = __floats2half2_rn(b.z, b.w);
    uint4 u;
    u.x = *reinterpret_cast<u32*>(&h0);
    u.y = *reinterpret_cast<u32*>(&h1);
    u.z = *reinterpret_cast<u32*>(&h2);
    u.w = *reinterpret_cast<u32*>(&h3);
    return u;
}
__device__ __forceinline__ void cpa16(u32 dst, const void* src) {
    asm volatile("cp.async.cg.shared.global [%0], [%1], 16;" :: "r"(dst), "l"(src));
}
__device__ __forceinline__ void cpa4(u32 dst, const void* src) {
    asm volatile("cp.async.ca.shared.global [%0], [%1], 4;" :: "r"(dst), "l"(src));
}
__device__ __forceinline__ void cpa_commit() {
    asm volatile("cp.async.commit_group;" ::: "memory");
}
template <int N>
__device__ __forceinline__ void cpa_wait() {
    asm volatile("cp.async.wait_group %0;" :: "n"(N) : "memory");
}

// log2(e) / sqrt(128): folded into Q so softmax uses raw EX2, no max needed
#define CFOLD 0.12751743f

extern __shared__ char smem_raw[];

// ---------------- kernel 1: wvo = w_output @ w_v; zero flag --------
__global__ void prep_kernel(const float* __restrict__ w_v,
                            const float* __restrict__ w_out) {
    int c = threadIdx.x;
    if (c == 0) g_x2sum = 0.0f;
    if (c < SRC) {
        float acc = 0.0f;
        #pragma unroll
        for (int j = 0; j < DV; j++) acc += w_out[j] * w_v[j * SRC + c];
        g_wvo[c] = acc;
    }
}

// ---------------- kernel 2: Q/K projections on HMMA + fused vscalar --
// Y[8192,128] = X[8192,768] @ W[128,768]^T, fp16 out (Q pre-scaled).
// CTA: 64 rows x 128 cols, K chunks of 64, 256 threads (8 warps,
// warp = 32 rows x 32 cols), 2 CTAs/SM. grid (128, 2).
#define PCH   12              /* 768 / 64 chunks */
#define OFF_XS  0             /* __half Xs[2][64][64]  = 16384 */
#define OFF_WS  16384         /* __half Ws[2][128][64] = 32768 */
#define OFF_WVS 49152         /* float wvs[768] = 3072 */
#define SMEM_PROJ 52224

__global__ void __launch_bounds__(256, 2)
proj_kernel(const float* __restrict__ x1, const float* __restrict__ x2,
            const float* __restrict__ wq, const float* __restrict__ wk) {
    const bool isQ = (blockIdx.y == 0);
    const float* X = isQ ? x1 : x2;
    const float* W = isQ ? wq : wk;
    __half* Y = isQ ? g_Qf : g_Kf;

    float* wvs = reinterpret_cast<float*>(smem_raw + OFF_WVS);

    const int tid = threadIdx.x, lane = tid & 31, w = tid >> 5;
    const int qg = w & 1;         // 32-row group (rows 0..63)
    const int nh = w >> 1;        // 32-col group (cols 0..127)
    const int r0 = blockIdx.x * 64;

    if (!isQ) {
        for (int i = tid; i < SRC; i += 256) wvs[i] = g_wvo[i];
    }
    __syncthreads();

    // staging: X 512 uint4 slots (2/thread), W 1024 slots (4/thread)
    int xrow[2], xch[2], wrow[4], wch[4];
    #pragma unroll
    for (int i = 0; i < 2; i++) {
        int idx = tid + i * 256;
        xrow[i] = idx >> 3;
        xch[i]  = idx & 7;
    }
    #pragma unroll
    for (int i = 0; i < 4; i++) {
        int idx = tid + i * 256;
        wrow[i] = idx >> 3;
        wch[i]  = idx & 7;
    }

    float vsacc[2] = {0.0f, 0.0f};
    float xsum = 0.0f;

    uint4 pX[2], pW[4];
    auto load_regs = [&](int kk) {
        #pragma unroll
        for (int i = 0; i < 2; i++) {
            const float* sx = &X[(size_t)(r0 + xrow[i]) * SRC + kk + xch[i] * 8];
            float4 a = *reinterpret_cast<const float4*>(sx);
            float4 b = *reinterpret_cast<const float4*>(sx + 4);
            if (!isQ) {
                const float* wv = &wvs[kk + xch[i] * 8];
                vsacc[i] = fmaf(a.x, wv[0], vsacc[i]);
                vsacc[i] = fmaf(a.y, wv[1], vsacc[i]);
                vsacc[i] = fmaf(a.z, wv[2], vsacc[i]);
                vsacc[i] = fmaf(a.w, wv[3], vsacc[i]);
                vsacc[i] = fmaf(b.x, wv[4], vsacc[i]);
                vsacc[i] = fmaf(b.y, wv[5], vsacc[i]);
                vsacc[i] = fmaf(b.z, wv[6], vsacc[i]);
                vsacc[i] = fmaf(b.w, wv[7], vsacc[i]);
                xsum += (a.x + a.y) + (a.z + a.w) + (b.x + b.y) + (b.z + b.w);
            }
            pX[i] = cvt8h(a, b);
        }
        #pragma unroll
        for (int i = 0; i < 4; i++) {
            const float* sw = &W[(size_t)wrow[i] * SRC + kk + wch[i] * 8];
            pW[i] = cvt8h(*reinterpret_cast<const float4*>(sw),
                          *reinterpret_cast<const float4*>(sw + 4));
        }
    };
    auto store_smem = [&](int buf) {
        char* xb = smem_raw + OFF_XS + buf * 8192;
        char* wb = smem_raw + OFF_WS + buf * 16384;
        #pragma unroll
        for (int i = 0; i < 2; i++) {
            u32 dst = (u32)(xrow[i] * 128) + (u32)((xch[i] ^ (xrow[i] & 7)) << 4);
            *reinterpret_cast<uint4*>(xb + dst) = pX[i];
        }
        #pragma unroll
        for (int i = 0; i < 4; i++) {
            u32 dst = (u32)(wrow[i] * 128) + (u32)((wch[i] ^ (wrow[i] & 7)) << 4);
            *reinterpret_cast<uint4*>(wb + dst) = pW[i];
        }
    };

    float c[2][4][4];
    #pragma unroll
    for (int mt = 0; mt < 2; mt++)
        #pragma unroll
        for (int j = 0; j < 4; j++)
            #pragma unroll
            for (int e = 0; e < 4; e++) c[mt][j][e] = 0.0f;

    const u32 sX = smem_u32(smem_raw) + OFF_XS;
    const u32 sW = smem_u32(smem_raw) + OFF_WS;
    const int rbA = qg * 32 + (lane & 7) + (lane & 8);
    const int kbitA = lane >> 4;
    const int rbB = nh * 32 + (lane & 7) + ((lane & 16) >> 1);
    const int kbitB = (lane >> 3) & 1;

    load_regs(0);
    for (int cidx = 0; cidx < PCH; cidx++) {
        const int buf = cidx & 1;
        store_smem(buf);
        __syncthreads();
        if (cidx + 1 < PCH) load_regs((cidx + 1) * 64);

        const u32 xb = sX + buf * 8192;
        const u32 wb = sW + buf * 16384;
        #pragma unroll
        for (int ks = 0; ks < 4; ks++) {
            u32 A0[4], A1[4];
            int chA = ks * 2 + kbitA;
            {
                int r = rbA;
                ldsm_x4(A0[0], A0[1], A0[2], A0[3], xb + r * 128 + ((chA ^ (r & 7)) << 4));
            }
            {
                int r = rbA + 16;
                ldsm_x4(A1[0], A1[1], A1[2], A1[3], xb + r * 128 + ((chA ^ (r & 7)) << 4));
            }
            int chB = ks * 2 + kbitB;
            #pragma unroll
            for (int nt = 0; nt < 2; nt++) {
                u32 b[4];
                int r = rbB + nt * 16;
                ldsm_x4(b[0], b[1], b[2], b[3], wb + r * 128 + ((chB ^ (r & 7)) << 4));
                mma16816(c[0][nt*2+0][0], c[0][nt*2+0][1], c[0][nt*2+0][2], c[0][nt*2+0][3],
                         A0[0], A0[1], A0[2], A0[3], b[0], b[1]);
                mma16816(c[0][nt*2+1][0], c[0][nt*2+1][1], c[0][nt*2+1][2], c[0][nt*2+1][3],
                         A0[0], A0[1], A0[2], A0[3], b[2], b[3]);
                mma16816(c[1][nt*2+0][0], c[1][nt*2+0][1], c[1][nt*2+0][2], c[1][nt*2+0][3],
                         A1[0], A1[1], A1[2], A1[3], b[0], b[1]);
                mma16816(c[1][nt*2+1][0], c[1][nt*2+1][1], c[1][nt*2+1][2], c[1][nt*2+1][3],
                         A1[0], A1[1], A1[2], A1[3], b[2], b[3]);
            }
        }
        __syncthreads();
    }

    if (!isQ) {
        #pragma unroll
        for (int m = 1; m < 8; m <<= 1) {
            vsacc[0] += __shfl_xor_sync(0xffffffffu, vsacc[0], m);
            vsacc[1] += __shfl_xor_sync(0xffffffffu, vsacc[1], m);
            xsum     += __shfl_xor_sync(0xffffffffu, xsum, m);
        }
        if ((lane & 7) == 0) {
            g_vs[r0 + xrow[0]] = vsacc[0];
            g_vs[r0 + xrow[1]] = vsacc[1];
            atomicAdd(&g_x2sum, xsum);
        }
    }

    const float scale = isQ ? CFOLD : 1.0f;
    #pragma unroll
    for (int mt = 0; mt < 2; mt++) {
        int row = r0 + qg * 32 + mt * 16 + (lane >> 2);
        #pragma unroll
        for (int j = 0; j < 4; j++) {
            int col = nh * 32 + j * 8 + (lane & 3) * 2;
            __half2 lo = __floats2half2_rn(c[mt][j][0] * scale, c[mt][j][1] * scale);
            __half2 hi = __floats2half2_rn(c[mt][j][2] * scale, c[mt][j][3] * scale);
            *reinterpret_cast<__half2*>(&Y[(size_t)row * DK + col]) = lo;
            *reinterpret_cast<__half2*>(&Y[(size_t)(row + 8) * DK + col]) = hi;
        }
    }
}

// ---------------- kernel 3: HMMA flash attention, f16 accumulators --
// CTA: 128 queries x 64-key tiles, 8 warps (warp = 32q x 32k).
// grid (64, KSPLIT). cp.async 3-stage K ring, 1 barrier/iter.
// Scores in fp16 HMMA, exp via ex2.f16x2, l/a accumulate in f16x2
// with per-tile fp32 flush.
#define OFF_KS   32768         /* __half Ks[3][64][128] */
#define OFF_VSB  81920         /* float vsb[3][64] */
#define OFF_RL   82688         /* float rl[2][128] */
#define OFF_RA   83712         /* float ra[2][128] */
#define SMEM_FLASH 84736

__global__ void __launch_bounds__(256, 2) flash_kernel() {
    float* vsb = reinterpret_cast<float*>(smem_raw + OFF_VSB);
    float* rl  = reinterpret_cast<float*>(smem_raw + OFF_RL);
    float* ra  = reinterpret_cast<float*>(smem_raw + OFF_RA);

    const int tid = threadIdx.x, lane = tid & 31, w = tid >> 5;
    const int q0 = blockIdx.x * 128;
    const int k0 = blockIdx.y * (S_N / KSPLIT);
    const int kh = w >> 2;       // key half within tile (0/1)
    const int qg = w & 3;        // 32-query group
    const u32 sbase = smem_u32(smem_raw);

    const int krow = tid >> 4, kch = tid & 15;

    auto issue_tile = [&](int it) {
        const int slot = it % 3;
        const int t0 = k0 + it * 64;
        #pragma unroll
        for (int i = 0; i < 4; i++) {
            int row = krow + i * 16;
            u32 dst = sbase + OFF_KS + slot * 16384 +
                      (u32)(row * 256) + (u32)((kch ^ (row & 7)) << 4);
            cpa16(dst, g_Kf + (size_t)(t0 + row) * DK + kch * 8);
        }
        if (tid < 64)
            cpa4(sbase + OFF_VSB + slot * 256 + tid * 4, &g_vs[t0 + tid]);
        cpa_commit();
    };

    issue_tile(0);
    issue_tile(1);

    // stage Q (XOR-swizzled)
    #pragma unroll
    for (int i = 0; i < 8; i++) {
        int idx = tid + i * 256;
        int row = idx >> 4, ch = idx & 15;
        u32 dst = (u32)(row * 256) + (u32)((ch ^ (row & 7)) << 4);
        *reinterpret_cast<uint4*>(smem_raw + dst) =
            *reinterpret_cast<const uint4*>(g_Qf + (size_t)(q0 + row) * DK + ch * 8);
    }
    __syncthreads();

    // A fragments: register-resident for the whole CTA lifetime
    u32 A[2][8][4];
    {
        int rb = qg * 32 + (lane & 7) + (lane & 8);
        int kbit = lane >> 4;
        #pragma unroll
        for (int mt = 0; mt < 2; mt++) {
            int row = rb + mt * 16;
            #pragma unroll
            for (int ks = 0; ks < 8; ks++) {
                int ch = ks * 2 + kbit;
                ldsm_x4(A[mt][ks][0], A[mt][ks][1], A[mt][ks][2], A[mt][ks][3],
                        sbase + row * 256 + ((ch ^ (row & 7)) << 4));
            }
        }
    }

    const u32 sK = sbase + OFF_KS;
    const int rB0 = kh * 32 + (lane & 7) + ((lane & 16) >> 1);
    const int kbitB = (lane >> 3) & 1;

    float l_[4] = {0, 0, 0, 0}, a_[4] = {0, 0, 0, 0};

    for (int it = 0; it < NIT; it++) {
        const int slot = it % 3;
        if (it + 1 < NIT) cpa_wait<1>(); else cpa_wait<0>();
        __syncthreads();
        if (it + 2 < NIT) issue_tile(it + 2);

        // ---- QK^T on tensor cores, fp16 accumulators ----
        u32 c2[2][4][2];
        #pragma unroll
        for (int mt = 0; mt < 2; mt++)
            #pragma unroll
            for (int j = 0; j < 4; j++) {
                c2[mt][j][0] = 0u;
                c2[mt][j][1] = 0u;
            }

        const u32 kb = sK + slot * 16384;
        #pragma unroll
        for (int ks = 0; ks < 8; ks++) {
            u32 b[8];
            int ch = ks * 2 + kbitB;
            {
                int row = rB0;
                ldsm_x4(b[0], b[1], b[2], b[3],
                        kb + row * 256 + ((ch ^ (row & 7)) << 4));
            }
            {
                int row = rB0 + 16;
                ldsm_x4(b[4], b[5], b[6], b[7],
                        kb + row * 256 + ((ch ^ (row & 7)) << 4));
            }
            #pragma unroll
            for (int mt = 0; mt < 2; mt++) {
                mma16816h(c2[mt][0][0], c2[mt][0][1],
                          A[mt][ks][0], A[mt][ks][1], A[mt][ks][2], A[mt][ks][3], b[0], b[1]);
                mma16816h(c2[mt][1][0], c2[mt][1][1],
                          A[mt][ks][0], A[mt][ks][1], A[mt][ks][2], A[mt][ks][3], b[2], b[3]);
                mma16816h(c2[mt][2][0], c2[mt][2][1],
                          A[mt][ks][0], A[mt][ks][1], A[mt][ks][2], A[mt][ks][3], b[4], b[5]);
                mma16816h(c2[mt][3][0], c2[mt][3][1],
                          A[mt][ks][0], A[mt][ks][1], A[mt][ks][2], A[mt][ks][3], b[6], b[7]);
            }
        }

        // ---- softmax accumulate: p = 2^s, f16x2 fma against packed v ----
        const float* vv = vsb + slot * 64 + kh * 32 + (lane & 3) * 2;
        u32 vs2h[4];
        #pragma unroll
        for (int j = 0; j < 4; j++) {
            float2 v2 = *reinterpret_cast<const float2*>(vv + j * 8);
            __half2 h = __floats2half2_rn(v2.x, v2.y);
            vs2h[j] = *reinterpret_cast<u32*>(&h);
        }
        u32 lh2[4] = {0u, 0u, 0u, 0u};
        u32 ah2[4] = {0u, 0u, 0u, 0u};
        #pragma unroll
        for (int j = 0; j < 4; j++) {
            #pragma unroll
            for (int mt = 0; mt < 2; mt++) {
                #pragma unroll
                for (int rr = 0; rr < 2; rr++) {
                    int r = mt * 2 + rr;
                    u32 p2 = ex2h2(c2[mt][j][rr]);
                    lh2[r] = hadd2u(lh2[r], p2);
                    ah2[r] = hfma2u(p2, vs2h[j], ah2[r]);
                }
            }
        }
        #pragma unroll
        for (int r = 0; r < 4; r++) {
            __half2 lh = *reinterpret_cast<__half2*>(&lh2[r]);
            l_[r] += __low2float(lh) + __high2float(lh);
            __half2 ah = *reinterpret_cast<__half2*>(&ah2[r]);
            a_[r] += __low2float(ah) + __high2float(ah);
        }
    }

    // quad reduce (lanes sharing a row are lane^1, lane^2)
    #pragma unroll
    for (int r = 0; r < 4; r++) {
        l_[r] += __shfl_xor_sync(0xffffffffu, l_[r], 1);
        l_[r] += __shfl_xor_sync(0xffffffffu, l_[r], 2);
        a_[r] += __shfl_xor_sync(0xffffffffu, a_[r], 1);
        a_[r] += __shfl_xor_sync(0xffffffffu, a_[r], 2);
    }
    __syncthreads();
    if ((lane & 3) == 0) {
        int gid = lane >> 2;
        #pragma unroll
        for (int r = 0; r < 4; r++) {
            int mt = r >> 1, rr = r & 1;
            int qrow = qg * 32 + mt * 16 + gid + rr * 8;
            rl[kh * 128 + qrow] = l_[r];
            ra[kh * 128 + qrow] = a_[r];
        }
    }
    __syncthreads();
    if (tid < 128) {
        int r = blockIdx.y * S_N + q0 + tid;
        g_pl[r] = rl[tid] + rl[128 + tid];
        g_pa[r] = ra[tid] + ra[128 + tid];
    }
}

// ---------------- kernel 4: fused combine + gate -------------------
// Block = 4 exact rows (768 float4), 256 threads x 3 independent float4.
__global__ void __launch_bounds__(256) gate_kernel(const float* __restrict__ x1,
                                                   float* __restrict__ y) {
    __shared__ float gs[4];
    const int b = blockIdx.x, tid = threadIdx.x;
    if (tid < 4) {
        int r = 4 * b + tid;
        float g = 0.0f;
        if (g_x2sum != 0.0f) {
            float L = 0.0f, A = 0.0f;
            #pragma unroll
            for (int s = 0; s < KSPLIT; s++) {
                L += g_pl[s * S_N + r];
                A += g_pa[s * S_N + r];
            }
            g = A / L;
        }
        gs[tid] = g;
    }
    __syncthreads();
    const float4* xin = reinterpret_cast<const float4*>(x1) + (size_t)b * 768;
    float4* yo = reinterpret_cast<float4*>(y) + (size_t)b * 768;
    float4 v[3];
    #pragma unroll
    for (int k = 0; k < 3; k++) v[k] = xin[tid + k * 256];
    #pragma unroll
    for (int k = 0; k < 3; k++) {
        int ro = (tid + k * 256) / 192;
        float f = 1.0f - gs[ro];
        v[k].x *= f; v[k].y *= f; v[k].z *= f; v[k].w *= f;
        yo[tid + k * 256] = v[k];
    }
}

// ---------------- launch ------------------------------------------
extern "C" void kernel_launch(void* const* d_in, const int* in_sizes, int n_in,
                              void* d_out, int out_size) {
    const float* x1 = (const float*)d_in[0];
    const float* x2 = (const float*)d_in[1];
    const float* wq = (const float*)d_in[2];
    const float* wk = (const float*)d_in[3];
    const float* wv = (const float*)d_in[4];
    const float* wo = (const float*)d_in[5];
    float* y = (float*)d_out;

    cudaFuncSetAttribute(flash_kernel, cudaFuncAttributeMaxDynamicSharedMemorySize,
                         SMEM_FLASH);
    cudaFuncSetAttribute(proj_kernel, cudaFuncAttributeMaxDynamicSharedMemorySize,
                         SMEM_PROJ);

    prep_kernel<<<1, 768>>>(wv, wo);
    proj_kernel<<<dim3(S_N / 64, 2), 256, SMEM_PROJ>>>(x1, x2, wq, wk);
    flash_kernel<<<dim3(S_N / 128, KSPLIT), 256, SMEM_FLASH>>>();
    gate_kernel<<<S_N / 4, 256>>>(x1, y);
}